// round 10
// baseline (speedup 1.0000x reference)
#include <cuda_runtime.h>
#include <cstdint>

// Problem constants
#define B_  4
#define S_  2048
#define D_  1024
#define H_  16
#define DK_ 64
#define M_  (B_*S_)   // 8192

// Scratch (device globals — no allocations allowed)
__device__ float g_Q[(size_t)B_*H_*S_*DK_];
__device__ float g_K[(size_t)B_*H_*S_*DK_];
__device__ float g_V[(size_t)B_*H_*S_*DK_];
__device__ float g_A[(size_t)B_*S_*D_];

__device__ __forceinline__ uint32_t f2tf32(float f) {
    uint32_t u;
    asm("cvt.rna.tf32.f32 %0, %1;" : "=r"(u) : "f"(f));
    return u;
}

__device__ __forceinline__ void mma_tf32(float d[4], const uint32_t a[4],
                                         const uint32_t b[2]) {
    asm volatile(
        "mma.sync.aligned.m16n8k8.row.col.f32.tf32.tf32.f32 "
        "{%0,%1,%2,%3}, {%4,%5,%6,%7}, {%8,%9}, {%0,%1,%2,%3};\n"
        : "+f"(d[0]), "+f"(d[1]), "+f"(d[2]), "+f"(d[3])
        : "r"(a[0]), "r"(a[1]), "r"(a[2]), "r"(a[3]),
          "r"(b[0]), "r"(b[1]));
}

// ============================================================================
// TF32 tensor-core GEMM, FRAGMENT-MAJOR dynamic smem: C = A @ W^T.
// Block 128x256, BK=32, 256 thr, 8 warps of 64x64. Staging split into two
// 16-col groups interleaved with the two compute half-steps (flat reg usage).
// Fragment positions (verified R7): A sub (r/16,k/8) idx lane*4+reg, stride 132;
// W sub (n/8,k/8) idx lane*2+reg, stride 66.
// MODE 0: C row-major [M,N]. MODE 1: split-heads epilogue.
// ============================================================================
#define BM 128
#define BN 256
#define BKG 32
#define AF_SB 132
#define BF_SB 66
#define AF_SZ (32 * AF_SB)    // per buffer: 8 mrow-blocks * 4 ks
#define BF_SZ (128 * BF_SB)   // per buffer: 32 nrow-blocks * 4 ks
#define GEMM_SMEM ((2 * AF_SZ + 2 * BF_SZ) * (int)sizeof(uint32_t))  // 101376 B

template<int MODE>
__device__ __forceinline__
void gemm_core(const float* __restrict__ A, const float* __restrict__ W,
               float* __restrict__ C, int M, int N, int K,
               int bx, int by) {
    extern __shared__ uint32_t dyn[];
    uint32_t* AF = dyn;                 // [2][AF_SZ]
    uint32_t* BF = dyn + 2 * AF_SZ;     // [2][BF_SZ]

    const int m0 = by * BM;
    const int n0 = bx * BN;
    const int tid = threadIdx.x;
    const int wid = tid >> 5;
    const int lane = tid & 31;

    const int wm0 = (wid & 1) * 64;    // warp m-origin (2 slots)
    const int wn0 = (wid >> 1) * 64;   // warp n-origin (4 slots)

    const int grow = tid >> 2;             // 0..63
    const int c40  = (tid & 3) << 2;       // 0,4,8,12
    const int rA   = (c40 >> 2) & 1;       // high-k half within a k-step

    float acc[4][8][4];
#pragma unroll
    for (int mt = 0; mt < 4; ++mt)
#pragma unroll
        for (int nt = 0; nt < 8; ++nt)
#pragma unroll
            for (int i = 0; i < 4; ++i) acc[mt][nt][i] = 0.f;

    const int NT = K / BKG;

    auto stA = [&](int buf, int r, int koff, float4 v) {
        const int ks2 = (c40 + koff) >> 3;
        const int base = buf * AF_SZ + ((r >> 4) * 4 + ks2) * AF_SB
                       + ((r & 7) * 4) * 4 + rA * 2 + ((r >> 3) & 1);
        AF[base     ] = f2tf32(v.x);
        AF[base +  4] = f2tf32(v.y);
        AF[base +  8] = f2tf32(v.z);
        AF[base + 12] = f2tf32(v.w);
    };
    auto stB = [&](int buf, int r, int koff, float4 v) {
        const int ks2 = (c40 + koff) >> 3;
        const int base = buf * BF_SZ + ((r >> 3) * 4 + ks2) * BF_SB
                       + ((r & 7) * 4) * 2 + rA;
        BF[base    ] = f2tf32(v.x);
        BF[base + 2] = f2tf32(v.y);
        BF[base + 4] = f2tf32(v.z);
        BF[base + 6] = f2tf32(v.w);
    };

    // One compute half-step: frag loads + 32 MMAs for one ks (0..3)
    auto compute_ks = [&](int cur, int ks) {
        uint4 av[4];
        uint2 bv[8];
#pragma unroll
        for (int mt = 0; mt < 4; ++mt)
            av[mt] = *(const uint4*)&AF[cur * AF_SZ
                    + (((wm0 >> 4) + mt) * 4 + ks) * AF_SB + lane * 4];
#pragma unroll
        for (int nt = 0; nt < 8; ++nt)
            bv[nt] = *(const uint2*)&BF[cur * BF_SZ
                    + (((wn0 >> 3) + nt) * 4 + ks) * BF_SB + lane * 2];
#pragma unroll
        for (int mt = 0; mt < 4; ++mt)
#pragma unroll
            for (int nt = 0; nt < 8; ++nt)
                mma_tf32(acc[mt][nt], (const uint32_t*)&av[mt],
                         (const uint32_t*)&bv[nt]);
    };

    // Prologue: stage tile 0 (both 16-col groups)
#pragma unroll
    for (int g = 0; g < 2; ++g) {
        const int koff = g * 16;
#pragma unroll
        for (int it = 0; it < 2; ++it) {
            int r = grow + it * 64;
            stA(0, r, koff, *(const float4*)(A + (size_t)(m0 + r) * K + koff + c40));
        }
#pragma unroll
        for (int it = 0; it < 4; ++it) {
            int r = grow + it * 64;
            stB(0, r, koff, *(const float4*)(W + (size_t)(n0 + r) * K + koff + c40));
        }
    }
    __syncthreads();

    for (int kt = 0; kt < NT; ++kt) {
        const int cur = kt & 1;
        const int nxt = cur ^ 1;
        const bool hn = (kt + 1 < NT);
        const int kb = (kt + 1) * BKG + c40;

        // Group 0: load next-tile cols [0,16)
        float4 pa[2], pb[4];
        if (hn) {
#pragma unroll
            for (int it = 0; it < 2; ++it)
                pa[it] = *(const float4*)(A + (size_t)(m0 + grow + it * 64) * K + kb);
#pragma unroll
            for (int it = 0; it < 4; ++it)
                pb[it] = *(const float4*)(W + (size_t)(n0 + grow + it * 64) * K + kb);
        }
        compute_ks(cur, 0);
        compute_ks(cur, 1);
        if (hn) {
#pragma unroll
            for (int it = 0; it < 2; ++it) stA(nxt, grow + it * 64, 0, pa[it]);
#pragma unroll
            for (int it = 0; it < 4; ++it) stB(nxt, grow + it * 64, 0, pb[it]);
            // Group 1: load next-tile cols [16,32)
#pragma unroll
            for (int it = 0; it < 2; ++it)
                pa[it] = *(const float4*)(A + (size_t)(m0 + grow + it * 64) * K + kb + 16);
#pragma unroll
            for (int it = 0; it < 4; ++it)
                pb[it] = *(const float4*)(W + (size_t)(n0 + grow + it * 64) * K + kb + 16);
        }
        compute_ks(cur, 2);
        compute_ks(cur, 3);
        if (hn) {
#pragma unroll
            for (int it = 0; it < 2; ++it) stA(nxt, grow + it * 64, 16, pa[it]);
#pragma unroll
            for (int it = 0; it < 4; ++it) stB(nxt, grow + it * 64, 16, pb[it]);
            __syncthreads();
        }
    }

    // Epilogue (c-frag: c0,c1 @(row,col..col+1); c2,c3 @(row+8,...))
    const int qr = lane >> 2;
    const int ql = lane & 3;
#pragma unroll
    for (int mt = 0; mt < 4; ++mt) {
#pragma unroll
        for (int nt = 0; nt < 8; ++nt) {
#pragma unroll
            for (int half = 0; half < 2; ++half) {
                int m = m0 + wm0 + mt * 16 + qr + half * 8;
                int n = n0 + wn0 + nt * 8 + ql * 2;
                float* p;
                if (MODE == 0) {
                    p = C + (size_t)m * N + n;
                } else {
                    int b  = m >> 11;
                    int s  = m & (S_ - 1);
                    int h  = n >> 6;
                    int dk = n & 63;
                    p = C + ((size_t)((b * H_ + h) * S_ + s)) * DK_ + dk;
                }
                *(float2*)p = make_float2(acc[mt][nt][half * 2],
                                          acc[mt][nt][half * 2 + 1]);
            }
        }
    }
}

__global__ __launch_bounds__(256, 1)
void gemm_qkv(const float* __restrict__ q, const float* __restrict__ k,
              const float* __restrict__ v,
              const float* __restrict__ Wq, const float* __restrict__ Wk,
              const float* __restrict__ Wv,
              float* __restrict__ Qo, float* __restrict__ Ko,
              float* __restrict__ Vo) {
    const float* A = (blockIdx.z == 0) ? q  : (blockIdx.z == 1) ? k  : v;
    const float* W = (blockIdx.z == 0) ? Wq : (blockIdx.z == 1) ? Wk : Wv;
    float*       C = (blockIdx.z == 0) ? Qo : (blockIdx.z == 1) ? Ko : Vo;
    gemm_core<1>(A, W, C, M_, D_, D_, blockIdx.x, blockIdx.y);
}

__global__ __launch_bounds__(256, 1)
void gemm_out(const float* __restrict__ A, const float* __restrict__ W,
              float* __restrict__ C) {
    gemm_core<0>(A, W, C, M_, D_, D_, blockIdx.x, blockIdx.y);
}

// ============================================================================
// Flash attention, TF32 mma, causal. QT=128 q-rows per block (256 thr,
// 8 warps x 16 rows), 64-col kv tiles. Branch-free global causal mask;
// fully-masked tiles skipped per-warp (barriers uniform).
// ============================================================================
#define ASTR_QKP 68
#define ASTR_V   72
#define ASM_Q  (128 * ASTR_QKP)
#define ASM_KP (128 * ASTR_QKP)
#define ASM_V  (64 * ASTR_V)
#define ATT_SMEM ((ASM_Q + ASM_KP + ASM_V) * (int)sizeof(uint32_t))  // 88064 B

__global__ __launch_bounds__(256)
void attn_mma(const float* __restrict__ Q, const float* __restrict__ K,
              const float* __restrict__ V, float* __restrict__ Out) {
    extern __shared__ uint32_t smw[];
    uint32_t* sQ  = smw;                    // [128][68] tf32
    uint32_t* sKP = smw + ASM_Q;            // K rows 0-63; P rows 0-127
    uint32_t* sV  = smw + ASM_Q + ASM_KP;   // [64][72]

    const int qt  = blockIdx.x;             // 0..15
    const int bh  = blockIdx.y;             // 0..63
    const int tid = threadIdx.x;
    const int wid = tid >> 5;               // 0..7
    const int lane = tid & 31;
    const int qr = lane >> 2;
    const int ql = lane & 3;
    const int wm = wid * 16;                // warp q-row origin (0..112)

    // Load Q tile (128 rows)
    {
        const float* Qg = Q + ((size_t)bh * S_ + qt * 128) * DK_;
#pragma unroll
        for (int it = 0; it < 8; ++it) {
            int f = tid + it * 256;          // 0..2047
            int row = f >> 4;                // 0..127
            int c4  = (f & 15) << 2;
            float4 v = *(const float4*)(Qg + row * 64 + c4);
            uint32_t* d = &sQ[row * ASTR_QKP + c4];
            d[0] = f2tf32(v.x); d[1] = f2tf32(v.y);
            d[2] = f2tf32(v.z); d[3] = f2tf32(v.w);
        }
    }

    float mrow0 = -1e30f, mrow1 = -1e30f, lrow0 = 0.f, lrow1 = 0.f;
    float o[8][4];
#pragma unroll
    for (int nt = 0; nt < 8; ++nt)
#pragma unroll
        for (int e = 0; e < 4; ++e) o[nt][e] = 0.f;

    const int rg0 = qt * 128 + wm + qr;     // global row of acc half 0
    const int rg1 = rg0 + 8;
    const int tmax = 2 * qt + 1;

    for (int t = 0; t <= tmax; ++t) {
        __syncthreads();  // prev PV readers done (t=0: Q store visibility)

        // Stage K (->sKP rows 0-63) and V (->sV), tf32
        const float* Kg = K + ((size_t)bh * S_ + t * 64) * DK_;
        const float* Vg = V + ((size_t)bh * S_ + t * 64) * DK_;
#pragma unroll
        for (int it = 0; it < 4; ++it) {
            int f = tid + it * 256;          // 0..1023
            int row = f >> 4;                // 0..63
            int c4  = (f & 15) << 2;
            float4 kv4 = *(const float4*)(Kg + row * 64 + c4);
            uint32_t* dk_ = &sKP[row * ASTR_QKP + c4];
            dk_[0] = f2tf32(kv4.x); dk_[1] = f2tf32(kv4.y);
            dk_[2] = f2tf32(kv4.z); dk_[3] = f2tf32(kv4.w);
            float4 vv4 = *(const float4*)(Vg + row * 64 + c4);
            uint32_t* dv_ = &sV[row * ASTR_V + c4];
            dv_[0] = f2tf32(vv4.x); dv_[1] = f2tf32(vv4.y);
            dv_[2] = f2tf32(vv4.z); dv_[3] = f2tf32(vv4.w);
        }
        __syncthreads();

        // Skip fully-masked tiles for this warp (cols all > last row)
        const bool active = (t * 64 <= qt * 128 + wm + 15);

        float sc[8][4];
        if (active) {
#pragma unroll
            for (int nt = 0; nt < 8; ++nt)
#pragma unroll
                for (int e = 0; e < 4; ++e) sc[nt][e] = 0.f;

#pragma unroll
            for (int k0 = 0; k0 < 64; k0 += 8) {
                uint32_t a[4];
                a[0] = sQ[(wm + qr    ) * ASTR_QKP + k0 + ql];
                a[1] = sQ[(wm + qr + 8) * ASTR_QKP + k0 + ql];
                a[2] = sQ[(wm + qr    ) * ASTR_QKP + k0 + ql + 4];
                a[3] = sQ[(wm + qr + 8) * ASTR_QKP + k0 + ql + 4];
#pragma unroll
                for (int nt = 0; nt < 8; ++nt) {
                    uint32_t b[2];
                    b[0] = sKP[(nt * 8 + qr) * ASTR_QKP + k0 + ql];
                    b[1] = sKP[(nt * 8 + qr) * ASTR_QKP + k0 + ql + 4];
                    mma_tf32(sc[nt], a, b);
                }
            }
        }
        __syncthreads();  // all K reads done before P overwrites sKP

        if (active) {
            // scale + branch-free causal mask + online softmax
            float tm0 = -1e30f, tm1 = -1e30f;
#pragma unroll
            for (int nt = 0; nt < 8; ++nt) {
                const int cg0 = t * 64 + nt * 8 + 2 * ql, cg1 = cg0 + 1;
#pragma unroll
                for (int e = 0; e < 4; ++e) sc[nt][e] *= 0.125f;
                if (cg0 > rg0) sc[nt][0] = -1e9f;
                if (cg1 > rg0) sc[nt][1] = -1e9f;
                if (cg0 > rg1) sc[nt][2] = -1e9f;
                if (cg1 > rg1) sc[nt][3] = -1e9f;
                tm0 = fmaxf(tm0, fmaxf(sc[nt][0], sc[nt][1]));
                tm1 = fmaxf(tm1, fmaxf(sc[nt][2], sc[nt][3]));
            }
            tm0 = fmaxf(tm0, __shfl_xor_sync(0xffffffffu, tm0, 1));
            tm0 = fmaxf(tm0, __shfl_xor_sync(0xffffffffu, tm0, 2));
            tm1 = fmaxf(tm1, __shfl_xor_sync(0xffffffffu, tm1, 1));
            tm1 = fmaxf(tm1, __shfl_xor_sync(0xffffffffu, tm1, 2));

            const float nm0 = fmaxf(mrow0, tm0);
            const float nm1 = fmaxf(mrow1, tm1);
            const float al0 = __expf(mrow0 - nm0);
            const float al1 = __expf(mrow1 - nm1);
            float sum0 = 0.f, sum1 = 0.f;
#pragma unroll
            for (int nt = 0; nt < 8; ++nt) {
                sc[nt][0] = __expf(sc[nt][0] - nm0);
                sc[nt][1] = __expf(sc[nt][1] - nm0);
                sc[nt][2] = __expf(sc[nt][2] - nm1);
                sc[nt][3] = __expf(sc[nt][3] - nm1);
                sum0 += sc[nt][0] + sc[nt][1];
                sum1 += sc[nt][2] + sc[nt][3];
            }
            sum0 += __shfl_xor_sync(0xffffffffu, sum0, 1);
            sum0 += __shfl_xor_sync(0xffffffffu, sum0, 2);
            sum1 += __shfl_xor_sync(0xffffffffu, sum1, 1);
            sum1 += __shfl_xor_sync(0xffffffffu, sum1, 2);

            lrow0 = lrow0 * al0 + sum0;
            lrow1 = lrow1 * al1 + sum1;
            mrow0 = nm0; mrow1 = nm1;

#pragma unroll
            for (int nt = 0; nt < 8; ++nt) {
                o[nt][0] *= al0; o[nt][1] *= al0;
                o[nt][2] *= al1; o[nt][3] *= al1;
            }

            // Store P (tf32) into sKP — warp-private rows
#pragma unroll
            for (int nt = 0; nt < 8; ++nt) {
                const int base0 = (wm + qr) * ASTR_QKP + nt * 8 + 2 * ql;
                sKP[base0]     = f2tf32(sc[nt][0]);
                sKP[base0 + 1] = f2tf32(sc[nt][1]);
                const int base1 = base0 + 8 * ASTR_QKP;
                sKP[base1]     = f2tf32(sc[nt][2]);
                sKP[base1 + 1] = f2tf32(sc[nt][3]);
            }
            __syncwarp();

            // PV: O += P @ V
#pragma unroll
            for (int k0 = 0; k0 < 64; k0 += 8) {
                uint32_t a[4];
                a[0] = sKP[(wm + qr    ) * ASTR_QKP + k0 + ql];
                a[1] = sKP[(wm + qr + 8) * ASTR_QKP + k0 + ql];
                a[2] = sKP[(wm + qr    ) * ASTR_QKP + k0 + ql + 4];
                a[3] = sKP[(wm + qr + 8) * ASTR_QKP + k0 + ql + 4];
#pragma unroll
                for (int nt = 0; nt < 8; ++nt) {
                    uint32_t b[2];
                    b[0] = sV[(k0 + ql    ) * ASTR_V + nt * 8 + qr];
                    b[1] = sV[(k0 + ql + 4) * ASTR_V + nt * 8 + qr];
                    mma_tf32(o[nt], a, b);
                }
            }
        }
    }

    // Epilogue -> [B,S,D]
    const float i0 = 1.f / lrow0, i1 = 1.f / lrow1;
    const int b = bh >> 4, h = bh & 15;
    const int s0 = qt * 128 + wm + qr, s1 = s0 + 8;
#pragma unroll
    for (int nt = 0; nt < 8; ++nt) {
        const int dk = nt * 8 + 2 * ql;
        float* p0 = Out + ((size_t)(b * S_ + s0)) * D_ + h * DK_ + dk;
        *(float2*)p0 = make_float2(o[nt][0] * i0, o[nt][1] * i0);
        float* p1 = Out + ((size_t)(b * S_ + s1)) * D_ + h * DK_ + dk;
        *(float2*)p1 = make_float2(o[nt][2] * i1, o[nt][3] * i1);
    }
}

// ============================================================================
// Launch
// ============================================================================
extern "C" void kernel_launch(void* const* d_in, const int* in_sizes, int n_in,
                              void* d_out, int out_size) {
    const float* q  = (const float*)d_in[0];
    const float* k  = (const float*)d_in[1];
    const float* v  = (const float*)d_in[2];
    // d_in[3] = mask (causal, known statically) — unused
    const float* Wq = (const float*)d_in[4];
    const float* Wk = (const float*)d_in[5];
    const float* Wv = (const float*)d_in[6];
    const float* Wo = (const float*)d_in[7];
    float* out = (float*)d_out;

    float *pQ, *pK, *pV, *pA;
    cudaGetSymbolAddress((void**)&pQ, g_Q);
    cudaGetSymbolAddress((void**)&pK, g_K);
    cudaGetSymbolAddress((void**)&pV, g_V);
    cudaGetSymbolAddress((void**)&pA, g_A);

    cudaFuncSetAttribute(gemm_qkv, cudaFuncAttributeMaxDynamicSharedMemorySize, GEMM_SMEM);
    cudaFuncSetAttribute(gemm_out, cudaFuncAttributeMaxDynamicSharedMemorySize, GEMM_SMEM);
    cudaFuncSetAttribute(attn_mma, cudaFuncAttributeMaxDynamicSharedMemorySize, ATT_SMEM);

    dim3 qkv_grid(D_ / BN, M_ / BM, 3);   // (4, 64, 3)
    gemm_qkv<<<qkv_grid, 256, GEMM_SMEM>>>(q, k, v, Wq, Wk, Wv, pQ, pK, pV);

    attn_mma<<<dim3(S_ / 128, B_ * H_), 256, ATT_SMEM>>>(pQ, pK, pV, pA);

    dim3 ogrid(D_ / BN, M_ / BM);         // (4, 64)
    gemm_out<<<ogrid, 256, GEMM_SMEM>>>(pA, Wo, out);
}

// round 11
// speedup vs baseline: 1.0398x; 1.0398x over previous
#include <cuda_runtime.h>
#include <cstdint>

// Problem constants
#define B_  4
#define S_  2048
#define D_  1024
#define H_  16
#define DK_ 64
#define M_  (B_*S_)   // 8192

// Scratch (device globals — no allocations allowed)
__device__ float g_Q[(size_t)B_*H_*S_*DK_];
__device__ float g_K[(size_t)B_*H_*S_*DK_];
__device__ float g_V[(size_t)B_*H_*S_*DK_];
__device__ float g_A[(size_t)B_*S_*D_];

__device__ __forceinline__ uint32_t f2tf32(float f) {
    uint32_t u;
    asm("cvt.rna.tf32.f32 %0, %1;" : "=r"(u) : "f"(f));
    return u;
}

__device__ __forceinline__ void mma_tf32(float d[4], const uint32_t a[4],
                                         const uint32_t b[2]) {
    asm volatile(
        "mma.sync.aligned.m16n8k8.row.col.f32.tf32.tf32.f32 "
        "{%0,%1,%2,%3}, {%4,%5,%6,%7}, {%8,%9}, {%0,%1,%2,%3};\n"
        : "+f"(d[0]), "+f"(d[1]), "+f"(d[2]), "+f"(d[3])
        : "r"(a[0]), "r"(a[1]), "r"(a[2]), "r"(a[3]),
          "r"(b[0]), "r"(b[1]));
}

__device__ __forceinline__ uint32_t smem_u32(const void* p) {
    uint32_t a;
    asm("{ .reg .u64 t; cvta.to.shared.u64 t, %1; cvt.u32.u64 %0, t; }"
        : "=r"(a) : "l"(p));
    return a;
}

__device__ __forceinline__ void cp16(uint32_t s, const void* g) {
    asm volatile("cp.async.cg.shared.global [%0], [%1], 16;\n"
                 :: "r"(s), "l"(g));
}
__device__ __forceinline__ void cp_commit() {
    asm volatile("cp.async.commit_group;\n" ::: "memory");
}
template<int N_> __device__ __forceinline__ void cp_wait() {
    asm volatile("cp.async.wait_group %0;\n" :: "n"(N_) : "memory");
}

// ============================================================================
// TF32 tensor-core GEMM, cp.async 3-stage pipeline: C = A @ W^T.
// A:[M,K] rm, W:[N,K] rm. Block 128x256, BK=16, 256 thr, 8 warps of 64x64.
// Smem holds raw fp32 rows (stride 20 floats, conflict-free scalar LDS);
// tf32 cvt in consumer (same values, same order => identical numerics).
// MODE 0: C row-major [M,N]. MODE 1: split-heads epilogue.
// ============================================================================
#define BM 128
#define BN 256
#define BKG 16
#define ALD 20
#define ABUF (BM * ALD)            // 2560 words / stage
#define BBUF (BN * ALD)            // 5120 words / stage
#define STG 3
#define STAGE_WORDS (ABUF + BBUF)  // 7680
#define GEMM_SMEM (STG * STAGE_WORDS * 4)   // 92160 B

template<int MODE>
__device__ __forceinline__
void gemm_core(const float* __restrict__ A, const float* __restrict__ W,
               float* __restrict__ C, int M, int N, int K,
               int bx, int by) {
    extern __shared__ uint32_t dyn[];
    const uint32_t sb = smem_u32(dyn);

    const int m0 = by * BM;
    const int n0 = bx * BN;
    const int tid = threadIdx.x;
    const int wid = tid >> 5;
    const int lane = tid & 31;
    const int qr = lane >> 2;
    const int ql = lane & 3;

    const int wm0 = (wid & 1) * 64;    // warp m-origin
    const int wn0 = (wid >> 1) * 64;   // warp n-origin

    const int grow = tid >> 2;             // 0..63
    const int c40  = (tid & 3) << 2;       // 0,4,8,12

    float acc[4][8][4];
#pragma unroll
    for (int mt = 0; mt < 4; ++mt)
#pragma unroll
        for (int nt = 0; nt < 8; ++nt)
#pragma unroll
            for (int i = 0; i < 4; ++i) acc[mt][nt][i] = 0.f;

    const int NT = K / BKG;

    auto issue = [&](int st, int kt) {
        const int k0 = kt * BKG;
        const uint32_t abase = sb + (uint32_t)(st * STAGE_WORDS) * 4u;
        const uint32_t bbase = abase + ABUF * 4u;
#pragma unroll
        for (int it = 0; it < 2; ++it) {
            int r = grow + it * 64;
            cp16(abase + (uint32_t)(r * ALD + c40) * 4u,
                 A + (size_t)(m0 + r) * K + k0 + c40);
        }
#pragma unroll
        for (int it = 0; it < 4; ++it) {
            int r = grow + it * 64;
            cp16(bbase + (uint32_t)(r * ALD + c40) * 4u,
                 W + (size_t)(n0 + r) * K + k0 + c40);
        }
    };

    // Prologue: stages 0..STG-2 in flight
#pragma unroll
    for (int s = 0; s < STG - 1; ++s) { issue(s, s); cp_commit(); }

    for (int kt = 0; kt < NT; ++kt) {
        cp_wait<STG - 2>();      // stage kt landed
        __syncthreads();         // all warps see it; prev compute done
        if (kt + STG - 1 < NT) issue((kt + STG - 1) % STG, kt + STG - 1);
        cp_commit();             // keep group count uniform (may be empty)

        const uint32_t* As = dyn + (kt % STG) * STAGE_WORDS;
        const uint32_t* Bs = As + ABUF;
#pragma unroll
        for (int ks = 0; ks < 2; ++ks) {
            const int kk = ks * 8;
            uint32_t a[4][4], b[8][2];
#pragma unroll
            for (int mt = 0; mt < 4; ++mt) {
                const int rb = wm0 + mt * 16 + qr;
                a[mt][0] = f2tf32(__uint_as_float(As[rb * ALD + kk + ql]));
                a[mt][1] = f2tf32(__uint_as_float(As[(rb + 8) * ALD + kk + ql]));
                a[mt][2] = f2tf32(__uint_as_float(As[rb * ALD + kk + ql + 4]));
                a[mt][3] = f2tf32(__uint_as_float(As[(rb + 8) * ALD + kk + ql + 4]));
            }
#pragma unroll
            for (int nt = 0; nt < 8; ++nt) {
                const int nb = wn0 + nt * 8 + qr;
                b[nt][0] = f2tf32(__uint_as_float(Bs[nb * ALD + kk + ql]));
                b[nt][1] = f2tf32(__uint_as_float(Bs[nb * ALD + kk + ql + 4]));
            }
#pragma unroll
            for (int mt = 0; mt < 4; ++mt)
#pragma unroll
                for (int nt = 0; nt < 8; ++nt)
                    mma_tf32(acc[mt][nt], a[mt], b[nt]);
        }
    }

    // Epilogue (c-frag: c0,c1 @(row,col..col+1); c2,c3 @(row+8,...))
#pragma unroll
    for (int mt = 0; mt < 4; ++mt) {
#pragma unroll
        for (int nt = 0; nt < 8; ++nt) {
#pragma unroll
            for (int half = 0; half < 2; ++half) {
                int m = m0 + wm0 + mt * 16 + qr + half * 8;
                int n = n0 + wn0 + nt * 8 + ql * 2;
                float* p;
                if (MODE == 0) {
                    p = C + (size_t)m * N + n;
                } else {
                    int b_ = m >> 11;
                    int s  = m & (S_ - 1);
                    int h  = n >> 6;
                    int dk = n & 63;
                    p = C + ((size_t)((b_ * H_ + h) * S_ + s)) * DK_ + dk;
                }
                *(float2*)p = make_float2(acc[mt][nt][half * 2],
                                          acc[mt][nt][half * 2 + 1]);
            }
        }
    }
}

__global__ __launch_bounds__(256, 1)
void gemm_qkv(const float* __restrict__ q, const float* __restrict__ k,
              const float* __restrict__ v,
              const float* __restrict__ Wq, const float* __restrict__ Wk,
              const float* __restrict__ Wv,
              float* __restrict__ Qo, float* __restrict__ Ko,
              float* __restrict__ Vo) {
    const float* A = (blockIdx.z == 0) ? q  : (blockIdx.z == 1) ? k  : v;
    const float* W = (blockIdx.z == 0) ? Wq : (blockIdx.z == 1) ? Wk : Wv;
    float*       C = (blockIdx.z == 0) ? Qo : (blockIdx.z == 1) ? Ko : Vo;
    gemm_core<1>(A, W, C, M_, D_, D_, blockIdx.x, blockIdx.y);
}

__global__ __launch_bounds__(256, 1)
void gemm_out(const float* __restrict__ A, const float* __restrict__ W,
              float* __restrict__ C) {
    gemm_core<0>(A, W, C, M_, D_, D_, blockIdx.x, blockIdx.y);
}

// ============================================================================
// Flash attention with TF32 tensor cores (reverted to the proven R5/R7
// version: 64 q-rows, 128 threads, 4 warps x 16 rows).
// ============================================================================
#define ASTR_QKP 68
#define ASTR_V   72
#define ASM_Q  (64 * ASTR_QKP)
#define ASM_KP (64 * ASTR_QKP)
#define ASM_V  (64 * ASTR_V)
#define ATT_SMEM ((ASM_Q + ASM_KP + ASM_V) * (int)sizeof(uint32_t))

__global__ __launch_bounds__(128)
void attn_mma(const float* __restrict__ Q, const float* __restrict__ K,
              const float* __restrict__ V, float* __restrict__ Out) {
    extern __shared__ uint32_t smw[];
    uint32_t* sQ  = smw;
    uint32_t* sKP = smw + ASM_Q;
    uint32_t* sV  = smw + ASM_Q + ASM_KP;

    const int qt  = blockIdx.x;
    const int bh  = blockIdx.y;
    const int tid = threadIdx.x;
    const int wid = tid >> 5;
    const int lane = tid & 31;
    const int qr = lane >> 2;
    const int ql = lane & 3;
    const int wm = wid * 16;

    {
        const float* Qg = Q + ((size_t)bh * S_ + qt * 64) * DK_;
#pragma unroll
        for (int it = 0; it < 8; ++it) {
            int f = tid + it * 128;
            int row = f >> 4;
            int c4  = (f & 15) << 2;
            float4 v = *(const float4*)(Qg + row * 64 + c4);
            uint32_t* d = &sQ[row * ASTR_QKP + c4];
            d[0] = f2tf32(v.x); d[1] = f2tf32(v.y);
            d[2] = f2tf32(v.z); d[3] = f2tf32(v.w);
        }
    }

    float mrow0 = -1e30f, mrow1 = -1e30f, lrow0 = 0.f, lrow1 = 0.f;
    float o[8][4];
#pragma unroll
    for (int nt = 0; nt < 8; ++nt)
#pragma unroll
        for (int e = 0; e < 4; ++e) o[nt][e] = 0.f;

    for (int t = 0; t <= qt; ++t) {
        __syncthreads();
        const float* Kg = K + ((size_t)bh * S_ + t * 64) * DK_;
        const float* Vg = V + ((size_t)bh * S_ + t * 64) * DK_;
#pragma unroll
        for (int it = 0; it < 8; ++it) {
            int f = tid + it * 128;
            int row = f >> 4;
            int c4  = (f & 15) << 2;
            float4 kv4 = *(const float4*)(Kg + row * 64 + c4);
            uint32_t* dk_ = &sKP[row * ASTR_QKP + c4];
            dk_[0] = f2tf32(kv4.x); dk_[1] = f2tf32(kv4.y);
            dk_[2] = f2tf32(kv4.z); dk_[3] = f2tf32(kv4.w);
            float4 vv4 = *(const float4*)(Vg + row * 64 + c4);
            uint32_t* dv_ = &sV[row * ASTR_V + c4];
            dv_[0] = f2tf32(vv4.x); dv_[1] = f2tf32(vv4.y);
            dv_[2] = f2tf32(vv4.z); dv_[3] = f2tf32(vv4.w);
        }
        __syncthreads();

        float sc[8][4];
#pragma unroll
        for (int nt = 0; nt < 8; ++nt)
#pragma unroll
            for (int e = 0; e < 4; ++e) sc[nt][e] = 0.f;

#pragma unroll
        for (int k0 = 0; k0 < 64; k0 += 8) {
            uint32_t a[4];
            a[0] = sQ[(wm + qr    ) * ASTR_QKP + k0 + ql];
            a[1] = sQ[(wm + qr + 8) * ASTR_QKP + k0 + ql];
            a[2] = sQ[(wm + qr    ) * ASTR_QKP + k0 + ql + 4];
            a[3] = sQ[(wm + qr + 8) * ASTR_QKP + k0 + ql + 4];
#pragma unroll
            for (int nt = 0; nt < 8; ++nt) {
                uint32_t b[2];
                b[0] = sKP[(nt * 8 + qr) * ASTR_QKP + k0 + ql];
                b[1] = sKP[(nt * 8 + qr) * ASTR_QKP + k0 + ql + 4];
                mma_tf32(sc[nt], a, b);
            }
        }
        __syncthreads();

        const int r0l = wm + qr, r1l = wm + qr + 8;
        float tm0 = -1e30f, tm1 = -1e30f;
#pragma unroll
        for (int nt = 0; nt < 8; ++nt) {
            const int c0 = nt * 8 + 2 * ql, c1 = c0 + 1;
#pragma unroll
            for (int e = 0; e < 4; ++e) sc[nt][e] *= 0.125f;
            if (t == qt) {
                if (c0 > r0l) sc[nt][0] = -1e9f;
                if (c1 > r0l) sc[nt][1] = -1e9f;
                if (c0 > r1l) sc[nt][2] = -1e9f;
                if (c1 > r1l) sc[nt][3] = -1e9f;
            }
            tm0 = fmaxf(tm0, fmaxf(sc[nt][0], sc[nt][1]));
            tm1 = fmaxf(tm1, fmaxf(sc[nt][2], sc[nt][3]));
        }
        tm0 = fmaxf(tm0, __shfl_xor_sync(0xffffffffu, tm0, 1));
        tm0 = fmaxf(tm0, __shfl_xor_sync(0xffffffffu, tm0, 2));
        tm1 = fmaxf(tm1, __shfl_xor_sync(0xffffffffu, tm1, 1));
        tm1 = fmaxf(tm1, __shfl_xor_sync(0xffffffffu, tm1, 2));

        const float nm0 = fmaxf(mrow0, tm0);
        const float nm1 = fmaxf(mrow1, tm1);
        const float al0 = __expf(mrow0 - nm0);
        const float al1 = __expf(mrow1 - nm1);
        float sum0 = 0.f, sum1 = 0.f;
#pragma unroll
        for (int nt = 0; nt < 8; ++nt) {
            sc[nt][0] = __expf(sc[nt][0] - nm0);
            sc[nt][1] = __expf(sc[nt][1] - nm0);
            sc[nt][2] = __expf(sc[nt][2] - nm1);
            sc[nt][3] = __expf(sc[nt][3] - nm1);
            sum0 += sc[nt][0] + sc[nt][1];
            sum1 += sc[nt][2] + sc[nt][3];
        }
        sum0 += __shfl_xor_sync(0xffffffffu, sum0, 1);
        sum0 += __shfl_xor_sync(0xffffffffu, sum0, 2);
        sum1 += __shfl_xor_sync(0xffffffffu, sum1, 1);
        sum1 += __shfl_xor_sync(0xffffffffu, sum1, 2);

        lrow0 = lrow0 * al0 + sum0;
        lrow1 = lrow1 * al1 + sum1;
        mrow0 = nm0; mrow1 = nm1;

#pragma unroll
        for (int nt = 0; nt < 8; ++nt) {
            o[nt][0] *= al0; o[nt][1] *= al0;
            o[nt][2] *= al1; o[nt][3] *= al1;
        }

#pragma unroll
        for (int nt = 0; nt < 8; ++nt) {
            const int base0 = (wm + qr) * ASTR_QKP + nt * 8 + 2 * ql;
            sKP[base0]     = f2tf32(sc[nt][0]);
            sKP[base0 + 1] = f2tf32(sc[nt][1]);
            const int base1 = base0 + 8 * ASTR_QKP;
            sKP[base1]     = f2tf32(sc[nt][2]);
            sKP[base1 + 1] = f2tf32(sc[nt][3]);
        }
        __syncwarp();

#pragma unroll
        for (int k0 = 0; k0 < 64; k0 += 8) {
            uint32_t a[4];
            a[0] = sKP[(wm + qr    ) * ASTR_QKP + k0 + ql];
            a[1] = sKP[(wm + qr + 8) * ASTR_QKP + k0 + ql];
            a[2] = sKP[(wm + qr    ) * ASTR_QKP + k0 + ql + 4];
            a[3] = sKP[(wm + qr + 8) * ASTR_QKP + k0 + ql + 4];
#pragma unroll
            for (int nt = 0; nt < 8; ++nt) {
                uint32_t b[2];
                b[0] = sV[(k0 + ql    ) * ASTR_V + nt * 8 + qr];
                b[1] = sV[(k0 + ql + 4) * ASTR_V + nt * 8 + qr];
                mma_tf32(o[nt], a, b);
            }
        }
    }

    const float i0 = 1.f / lrow0, i1 = 1.f / lrow1;
    const int b = bh >> 4, h = bh & 15;
    const int s0 = qt * 64 + wm + qr, s1 = s0 + 8;
#pragma unroll
    for (int nt = 0; nt < 8; ++nt) {
        const int dk = nt * 8 + 2 * ql;
        float* p0 = Out + ((size_t)(b * S_ + s0)) * D_ + h * DK_ + dk;
        *(float2*)p0 = make_float2(o[nt][0] * i0, o[nt][1] * i0);
        float* p1 = Out + ((size_t)(b * S_ + s1)) * D_ + h * DK_ + dk;
        *(float2*)p1 = make_float2(o[nt][2] * i1, o[nt][3] * i1);
    }
}

// ============================================================================
// Launch
// ============================================================================
extern "C" void kernel_launch(void* const* d_in, const int* in_sizes, int n_in,
                              void* d_out, int out_size) {
    const float* q  = (const float*)d_in[0];
    const float* k  = (const float*)d_in[1];
    const float* v  = (const float*)d_in[2];
    // d_in[3] = mask (causal, known statically) — unused
    const float* Wq = (const float*)d_in[4];
    const float* Wk = (const float*)d_in[5];
    const float* Wv = (const float*)d_in[6];
    const float* Wo = (const float*)d_in[7];
    float* out = (float*)d_out;

    float *pQ, *pK, *pV, *pA;
    cudaGetSymbolAddress((void**)&pQ, g_Q);
    cudaGetSymbolAddress((void**)&pK, g_K);
    cudaGetSymbolAddress((void**)&pV, g_V);
    cudaGetSymbolAddress((void**)&pA, g_A);

    cudaFuncSetAttribute(gemm_qkv, cudaFuncAttributeMaxDynamicSharedMemorySize, GEMM_SMEM);
    cudaFuncSetAttribute(gemm_out, cudaFuncAttributeMaxDynamicSharedMemorySize, GEMM_SMEM);
    cudaFuncSetAttribute(attn_mma, cudaFuncAttributeMaxDynamicSharedMemorySize, ATT_SMEM);

    dim3 qkv_grid(D_ / BN, M_ / BM, 3);   // (4, 64, 3)
    gemm_qkv<<<qkv_grid, 256, GEMM_SMEM>>>(q, k, v, Wq, Wk, Wv, pQ, pK, pV);

    attn_mma<<<dim3(S_ / 64, B_ * H_), 128, ATT_SMEM>>>(pQ, pK, pV, pA);

    dim3 ogrid(D_ / BN, M_ / BM);         // (4, 64)
    gemm_out<<<ogrid, 256, GEMM_SMEM>>>(pA, Wo, out);
}

// round 13
// speedup vs baseline: 1.2227x; 1.1759x over previous
#include <cuda_runtime.h>
#include <cuda_fp16.h>
#include <cstdint>

// Problem constants
#define B_  4
#define S_  2048
#define D_  1024
#define H_  16
#define DK_ 64
#define M_  (B_*S_)   // 8192

// Scratch (device globals — no allocations allowed)
__device__ float g_Q[(size_t)B_*H_*S_*DK_];
__device__ float g_K[(size_t)B_*H_*S_*DK_];
__device__ float g_V[(size_t)B_*H_*S_*DK_];
__device__ float g_A[(size_t)B_*S_*D_];

__device__ __forceinline__ uint32_t f2tf32(float f) {
    uint32_t u;
    asm("cvt.rna.tf32.f32 %0, %1;" : "=r"(u) : "f"(f));
    return u;
}
__device__ __forceinline__ uint32_t packh2(float x, float y) {
    __half2 h = __floats2half2_rn(x, y);
    return *(uint32_t*)&h;
}

__device__ __forceinline__ void mma_tf32(float d[4], const uint32_t a[4],
                                         const uint32_t b[2]) {
    asm volatile(
        "mma.sync.aligned.m16n8k8.row.col.f32.tf32.tf32.f32 "
        "{%0,%1,%2,%3}, {%4,%5,%6,%7}, {%8,%9}, {%0,%1,%2,%3};\n"
        : "+f"(d[0]), "+f"(d[1]), "+f"(d[2]), "+f"(d[3])
        : "r"(a[0]), "r"(a[1]), "r"(a[2]), "r"(a[3]),
          "r"(b[0]), "r"(b[1]));
}

__device__ __forceinline__ void mma_f16(float d[4], const uint32_t a[4],
                                        const uint32_t b[2]) {
    asm volatile(
        "mma.sync.aligned.m16n8k16.row.col.f32.f16.f16.f32 "
        "{%0,%1,%2,%3}, {%4,%5,%6,%7}, {%8,%9}, {%0,%1,%2,%3};\n"
        : "+f"(d[0]), "+f"(d[1]), "+f"(d[2]), "+f"(d[3])
        : "r"(a[0]), "r"(a[1]), "r"(a[2]), "r"(a[3]),
          "r"(b[0]), "r"(b[1]));
}

// ============================================================================
// FP16 tensor-core GEMM (m16n8k16), FRAGMENT-MAJOR static smem: C = A @ W^T.
// A:[M,K] rm, W:[N,K] rm. Block 128x256, BK=16 (one k16 step), 256 thr,
// 8 warps of 64x64. fp16 has the same 10-bit mantissa as tf32; fp32 accum.
// Fragment positions (m16n8k16, k-pairs packed in half2):
//   A: sub (r/16): b32 idx = lane*4 + reg, reg=(k>=8)*2+(r%16>=8),
//      lane=(r%8)*4+(k%8)/2, halves = k%2. Sub stride 132 -> LDS.128 consumer.
//   W: sub (n/8):  b32 idx = lane*2 + reg, reg=(k>=8),
//      lane=(n%8)*4+(k%8)/2. Sub stride 66 -> LDS.64 consumer.
// MODE 0: C row-major [M,N]. MODE 1: split-heads epilogue.
// ============================================================================
#define BM 128
#define BN 256
#define AF_SB 132
#define BF_SB 66
#define AF_SZ (8 * AF_SB)     // 1056 b32 per buffer
#define BF_SZ (32 * BF_SB)    // 2112 b32 per buffer

template<int MODE>
__device__ __forceinline__
void gemm_core(const float* __restrict__ A, const float* __restrict__ W,
               float* __restrict__ C, int M, int N, int K,
               int bx, int by) {
    __shared__ uint32_t AF[2][AF_SZ];
    __shared__ uint32_t BF[2][BF_SZ];

    const int m0 = by * BM;
    const int n0 = bx * BN;
    const int tid = threadIdx.x;
    const int wid = tid >> 5;
    const int lane = tid & 31;
    const int qr = lane >> 2;
    const int ql = lane & 3;

    const int wm0 = (wid & 1) * 64;    // warp m-origin
    const int wn0 = (wid >> 1) * 64;   // warp n-origin

    const int grow = tid >> 2;             // 0..63
    const int c40  = (tid & 3) << 2;       // 0,4,8,12
    const int lf0  = (c40 & 7) >> 1;       // k-pair offset within sub-lane

    float acc[4][8][4];
#pragma unroll
    for (int mt = 0; mt < 4; ++mt)
#pragma unroll
        for (int nt = 0; nt < 8; ++nt)
#pragma unroll
            for (int i = 0; i < 4; ++i) acc[mt][nt][i] = 0.f;

    const int NT = K / 16;

    auto stA = [&](int buf, int r, float4 v) {
        const int reg  = ((c40 & 8) ? 2 : 0) + (((r & 15) >= 8) ? 1 : 0);
        const int base = (r >> 4) * AF_SB + ((r & 7) * 4 + lf0) * 4 + reg;
        AF[buf][base    ] = packh2(v.x, v.y);
        AF[buf][base + 4] = packh2(v.z, v.w);
    };
    auto stB = [&](int buf, int r, float4 v) {
        const int reg  = (c40 & 8) ? 1 : 0;
        const int base = (r >> 3) * BF_SB + ((r & 7) * 4 + lf0) * 2 + reg;
        BF[buf][base    ] = packh2(v.x, v.y);
        BF[buf][base + 2] = packh2(v.z, v.w);
    };

    // Prologue: stage tile 0
#pragma unroll
    for (int it = 0; it < 2; ++it) {
        int r = grow + it * 64;
        stA(0, r, *(const float4*)(A + (size_t)(m0 + r) * K + c40));
    }
#pragma unroll
    for (int it = 0; it < 4; ++it) {
        int r = grow + it * 64;
        stB(0, r, *(const float4*)(W + (size_t)(n0 + r) * K + c40));
    }
    __syncthreads();

    for (int kt = 0; kt < NT; ++kt) {
        const int cur = kt & 1;

        // Prefetch next tile gmem -> regs
        float4 pa[2], pb[4];
        if (kt + 1 < NT) {
            const int k0 = (kt + 1) * 16;
#pragma unroll
            for (int it = 0; it < 2; ++it) {
                int r = grow + it * 64;
                pa[it] = *(const float4*)(A + (size_t)(m0 + r) * K + k0 + c40);
            }
#pragma unroll
            for (int it = 0; it < 4; ++it) {
                int r = grow + it * 64;
                pb[it] = *(const float4*)(W + (size_t)(n0 + r) * K + k0 + c40);
            }
        }

        // Compute: ONE k16 step, wide fragment loads, 32 MMAs
        {
            uint4 av[4];
            uint2 bv[8];
#pragma unroll
            for (int mt = 0; mt < 4; ++mt)
                av[mt] = *(const uint4*)&AF[cur][(((wm0 >> 4) + mt)) * AF_SB + lane * 4];
#pragma unroll
            for (int nt = 0; nt < 8; ++nt)
                bv[nt] = *(const uint2*)&BF[cur][(((wn0 >> 3) + nt)) * BF_SB + lane * 2];
#pragma unroll
            for (int mt = 0; mt < 4; ++mt)
#pragma unroll
                for (int nt = 0; nt < 8; ++nt)
                    mma_f16(acc[mt][nt], (const uint32_t*)&av[mt],
                            (const uint32_t*)&bv[nt]);
        }

        // Store prefetched tile to the other buffer
        if (kt + 1 < NT) {
            const int nxt = cur ^ 1;
#pragma unroll
            for (int it = 0; it < 2; ++it) stA(nxt, grow + it * 64, pa[it]);
#pragma unroll
            for (int it = 0; it < 4; ++it) stB(nxt, grow + it * 64, pb[it]);
            __syncthreads();
        }
    }

    // Epilogue (c-frag: c0,c1 @(row,col..col+1); c2,c3 @(row+8,...))
#pragma unroll
    for (int mt = 0; mt < 4; ++mt) {
#pragma unroll
        for (int nt = 0; nt < 8; ++nt) {
#pragma unroll
            for (int half = 0; half < 2; ++half) {
                int m = m0 + wm0 + mt * 16 + qr + half * 8;
                int n = n0 + wn0 + nt * 8 + ql * 2;
                float* p;
                if (MODE == 0) {
                    p = C + (size_t)m * N + n;
                } else {
                    int b  = m >> 11;
                    int s  = m & (S_ - 1);
                    int h  = n >> 6;
                    int dk = n & 63;
                    p = C + ((size_t)((b * H_ + h) * S_ + s)) * DK_ + dk;
                }
                *(float2*)p = make_float2(acc[mt][nt][half * 2],
                                          acc[mt][nt][half * 2 + 1]);
            }
        }
    }
}

__global__ __launch_bounds__(256, 1)
void gemm_qkv(const float* __restrict__ q, const float* __restrict__ k,
              const float* __restrict__ v,
              const float* __restrict__ Wq, const float* __restrict__ Wk,
              const float* __restrict__ Wv,
              float* __restrict__ Qo, float* __restrict__ Ko,
              float* __restrict__ Vo) {
    const float* A = (blockIdx.z == 0) ? q  : (blockIdx.z == 1) ? k  : v;
    const float* W = (blockIdx.z == 0) ? Wq : (blockIdx.z == 1) ? Wk : Wv;
    float*       C = (blockIdx.z == 0) ? Qo : (blockIdx.z == 1) ? Ko : Vo;
    gemm_core<1>(A, W, C, M_, D_, D_, blockIdx.x, blockIdx.y);
}

__global__ __launch_bounds__(256, 1)
void gemm_out(const float* __restrict__ A, const float* __restrict__ W,
              float* __restrict__ C) {
    gemm_core<0>(A, W, C, M_, D_, D_, blockIdx.x, blockIdx.y);
}

// ============================================================================
// Flash attention with TF32 tensor cores (proven R5 version, unchanged).
// ============================================================================
#define ASTR_QKP 68
#define ASTR_V   72
#define ASM_Q  (64 * ASTR_QKP)
#define ASM_KP (64 * ASTR_QKP)
#define ASM_V  (64 * ASTR_V)
#define ATT_SMEM ((ASM_Q + ASM_KP + ASM_V) * (int)sizeof(uint32_t))

__global__ __launch_bounds__(128)
void attn_mma(const float* __restrict__ Q, const float* __restrict__ K,
              const float* __restrict__ V, float* __restrict__ Out) {
    extern __shared__ uint32_t smw[];
    uint32_t* sQ  = smw;
    uint32_t* sKP = smw + ASM_Q;
    uint32_t* sV  = smw + ASM_Q + ASM_KP;

    const int qt  = blockIdx.x;
    const int bh  = blockIdx.y;
    const int tid = threadIdx.x;
    const int wid = tid >> 5;
    const int lane = tid & 31;
    const int qr = lane >> 2;
    const int ql = lane & 3;
    const int wm = wid * 16;

    {
        const float* Qg = Q + ((size_t)bh * S_ + qt * 64) * DK_;
#pragma unroll
        for (int it = 0; it < 8; ++it) {
            int f = tid + it * 128;
            int row = f >> 4;
            int c4  = (f & 15) << 2;
            float4 v = *(const float4*)(Qg + row * 64 + c4);
            uint32_t* d = &sQ[row * ASTR_QKP + c4];
            d[0] = f2tf32(v.x); d[1] = f2tf32(v.y);
            d[2] = f2tf32(v.z); d[3] = f2tf32(v.w);
        }
    }

    float mrow0 = -1e30f, mrow1 = -1e30f, lrow0 = 0.f, lrow1 = 0.f;
    float o[8][4];
#pragma unroll
    for (int nt = 0; nt < 8; ++nt)
#pragma unroll
        for (int e = 0; e < 4; ++e) o[nt][e] = 0.f;

    for (int t = 0; t <= qt; ++t) {
        __syncthreads();
        const float* Kg = K + ((size_t)bh * S_ + t * 64) * DK_;
        const float* Vg = V + ((size_t)bh * S_ + t * 64) * DK_;
#pragma unroll
        for (int it = 0; it < 8; ++it) {
            int f = tid + it * 128;
            int row = f >> 4;
            int c4  = (f & 15) << 2;
            float4 kv4 = *(const float4*)(Kg + row * 64 + c4);
            uint32_t* dk_ = &sKP[row * ASTR_QKP + c4];
            dk_[0] = f2tf32(kv4.x); dk_[1] = f2tf32(kv4.y);
            dk_[2] = f2tf32(kv4.z); dk_[3] = f2tf32(kv4.w);
            float4 vv4 = *(const float4*)(Vg + row * 64 + c4);
            uint32_t* dv_ = &sV[row * ASTR_V + c4];
            dv_[0] = f2tf32(vv4.x); dv_[1] = f2tf32(vv4.y);
            dv_[2] = f2tf32(vv4.z); dv_[3] = f2tf32(vv4.w);
        }
        __syncthreads();

        float sc[8][4];
#pragma unroll
        for (int nt = 0; nt < 8; ++nt)
#pragma unroll
            for (int e = 0; e < 4; ++e) sc[nt][e] = 0.f;

#pragma unroll
        for (int k0 = 0; k0 < 64; k0 += 8) {
            uint32_t a[4];
            a[0] = sQ[(wm + qr    ) * ASTR_QKP + k0 + ql];
            a[1] = sQ[(wm + qr + 8) * ASTR_QKP + k0 + ql];
            a[2] = sQ[(wm + qr    ) * ASTR_QKP + k0 + ql + 4];
            a[3] = sQ[(wm + qr + 8) * ASTR_QKP + k0 + ql + 4];
#pragma unroll
            for (int nt = 0; nt < 8; ++nt) {
                uint32_t b[2];
                b[0] = sKP[(nt * 8 + qr) * ASTR_QKP + k0 + ql];
                b[1] = sKP[(nt * 8 + qr) * ASTR_QKP + k0 + ql + 4];
                mma_tf32(sc[nt], a, b);
            }
        }
        __syncthreads();

        const int r0l = wm + qr, r1l = wm + qr + 8;
        float tm0 = -1e30f, tm1 = -1e30f;
#pragma unroll
        for (int nt = 0; nt < 8; ++nt) {
            const int c0 = nt * 8 + 2 * ql, c1 = c0 + 1;
#pragma unroll
            for (int e = 0; e < 4; ++e) sc[nt][e] *= 0.125f;
            if (t == qt) {
                if (c0 > r0l) sc[nt][0] = -1e9f;
                if (c1 > r0l) sc[nt][1] = -1e9f;
                if (c0 > r1l) sc[nt][2] = -1e9f;
                if (c1 > r1l) sc[nt][3] = -1e9f;
            }
            tm0 = fmaxf(tm0, fmaxf(sc[nt][0], sc[nt][1]));
            tm1 = fmaxf(tm1, fmaxf(sc[nt][2], sc[nt][3]));
        }
        tm0 = fmaxf(tm0, __shfl_xor_sync(0xffffffffu, tm0, 1));
        tm0 = fmaxf(tm0, __shfl_xor_sync(0xffffffffu, tm0, 2));
        tm1 = fmaxf(tm1, __shfl_xor_sync(0xffffffffu, tm1, 1));
        tm1 = fmaxf(tm1, __shfl_xor_sync(0xffffffffu, tm1, 2));

        const float nm0 = fmaxf(mrow0, tm0);
        const float nm1 = fmaxf(mrow1, tm1);
        const float al0 = __expf(mrow0 - nm0);
        const float al1 = __expf(mrow1 - nm1);
        float sum0 = 0.f, sum1 = 0.f;
#pragma unroll
        for (int nt = 0; nt < 8; ++nt) {
            sc[nt][0] = __expf(sc[nt][0] - nm0);
            sc[nt][1] = __expf(sc[nt][1] - nm0);
            sc[nt][2] = __expf(sc[nt][2] - nm1);
            sc[nt][3] = __expf(sc[nt][3] - nm1);
            sum0 += sc[nt][0] + sc[nt][1];
            sum1 += sc[nt][2] + sc[nt][3];
        }
        sum0 += __shfl_xor_sync(0xffffffffu, sum0, 1);
        sum0 += __shfl_xor_sync(0xffffffffu, sum0, 2);
        sum1 += __shfl_xor_sync(0xffffffffu, sum1, 1);
        sum1 += __shfl_xor_sync(0xffffffffu, sum1, 2);

        lrow0 = lrow0 * al0 + sum0;
        lrow1 = lrow1 * al1 + sum1;
        mrow0 = nm0; mrow1 = nm1;

#pragma unroll
        for (int nt = 0; nt < 8; ++nt) {
            o[nt][0] *= al0; o[nt][1] *= al0;
            o[nt][2] *= al1; o[nt][3] *= al1;
        }

#pragma unroll
        for (int nt = 0; nt < 8; ++nt) {
            const int base0 = (wm + qr) * ASTR_QKP + nt * 8 + 2 * ql;
            sKP[base0]     = f2tf32(sc[nt][0]);
            sKP[base0 + 1] = f2tf32(sc[nt][1]);
            const int base1 = base0 + 8 * ASTR_QKP;
            sKP[base1]     = f2tf32(sc[nt][2]);
            sKP[base1 + 1] = f2tf32(sc[nt][3]);
        }
        __syncwarp();

#pragma unroll
        for (int k0 = 0; k0 < 64; k0 += 8) {
            uint32_t a[4];
            a[0] = sKP[(wm + qr    ) * ASTR_QKP + k0 + ql];
            a[1] = sKP[(wm + qr + 8) * ASTR_QKP + k0 + ql];
            a[2] = sKP[(wm + qr    ) * ASTR_QKP + k0 + ql + 4];
            a[3] = sKP[(wm + qr + 8) * ASTR_QKP + k0 + ql + 4];
#pragma unroll
            for (int nt = 0; nt < 8; ++nt) {
                uint32_t b[2];
                b[0] = sV[(k0 + ql    ) * ASTR_V + nt * 8 + qr];
                b[1] = sV[(k0 + ql + 4) * ASTR_V + nt * 8 + qr];
                mma_tf32(o[nt], a, b);
            }
        }
    }

    const float i0 = 1.f / lrow0, i1 = 1.f / lrow1;
    const int b = bh >> 4, h = bh & 15;
    const int s0 = qt * 64 + wm + qr, s1 = s0 + 8;
#pragma unroll
    for (int nt = 0; nt < 8; ++nt) {
        const int dk = nt * 8 + 2 * ql;
        float* p0 = Out + ((size_t)(b * S_ + s0)) * D_ + h * DK_ + dk;
        *(float2*)p0 = make_float2(o[nt][0] * i0, o[nt][1] * i0);
        float* p1 = Out + ((size_t)(b * S_ + s1)) * D_ + h * DK_ + dk;
        *(float2*)p1 = make_float2(o[nt][2] * i1, o[nt][3] * i1);
    }
}

// ============================================================================
// Launch
// ============================================================================
extern "C" void kernel_launch(void* const* d_in, const int* in_sizes, int n_in,
                              void* d_out, int out_size) {
    const float* q  = (const float*)d_in[0];
    const float* k  = (const float*)d_in[1];
    const float* v  = (const float*)d_in[2];
    // d_in[3] = mask (causal, known statically) — unused
    const float* Wq = (const float*)d_in[4];
    const float* Wk = (const float*)d_in[5];
    const float* Wv = (const float*)d_in[6];
    const float* Wo = (const float*)d_in[7];
    float* out = (float*)d_out;

    float *pQ, *pK, *pV, *pA;
    cudaGetSymbolAddress((void**)&pQ, g_Q);
    cudaGetSymbolAddress((void**)&pK, g_K);
    cudaGetSymbolAddress((void**)&pV, g_V);
    cudaGetSymbolAddress((void**)&pA, g_A);

    cudaFuncSetAttribute(attn_mma, cudaFuncAttributeMaxDynamicSharedMemorySize, ATT_SMEM);

    dim3 qkv_grid(D_ / BN, M_ / BM, 3);   // (4, 64, 3)
    gemm_qkv<<<qkv_grid, 256>>>(q, k, v, Wq, Wk, Wv, pQ, pK, pV);

    attn_mma<<<dim3(S_ / 64, B_ * H_), 128, ATT_SMEM>>>(pQ, pK, pV, pA);

    dim3 ogrid(D_ / BN, M_ / BM);         // (4, 64)
    gemm_out<<<ogrid, 256>>>(pA, Wo, out);
}

// round 14
// speedup vs baseline: 1.4391x; 1.1770x over previous
#include <cuda_runtime.h>
#include <cuda_fp16.h>
#include <cstdint>

// Problem constants
#define B_  4
#define S_  2048
#define D_  1024
#define H_  16
#define DK_ 64
#define M_  (B_*S_)   // 8192

// Scratch (device globals — no allocations allowed)
__device__ float g_Q[(size_t)B_*H_*S_*DK_];
__device__ float g_K[(size_t)B_*H_*S_*DK_];
__device__ float g_V[(size_t)B_*H_*S_*DK_];
__device__ float g_A[(size_t)B_*S_*D_];

__device__ __forceinline__ uint32_t packh2(float x, float y) {
    __half2 h = __floats2half2_rn(x, y);
    return *(uint32_t*)&h;
}

__device__ __forceinline__ void mma_f16(float d[4], const uint32_t a[4],
                                        const uint32_t b[2]) {
    asm volatile(
        "mma.sync.aligned.m16n8k16.row.col.f32.f16.f16.f32 "
        "{%0,%1,%2,%3}, {%4,%5,%6,%7}, {%8,%9}, {%0,%1,%2,%3};\n"
        : "+f"(d[0]), "+f"(d[1]), "+f"(d[2]), "+f"(d[3])
        : "r"(a[0]), "r"(a[1]), "r"(a[2]), "r"(a[3]),
          "r"(b[0]), "r"(b[1]));
}

// ============================================================================
// FP16 tensor-core GEMM (m16n8k16), FRAGMENT-MAJOR static smem: C = A @ W^T.
// (unchanged from passing R13 kernel: 355us qkv)
// ============================================================================
#define BM 128
#define BN 256
#define AF_SB 132
#define BF_SB 66
#define AF_SZ (8 * AF_SB)
#define BF_SZ (32 * BF_SB)

template<int MODE>
__device__ __forceinline__
void gemm_core(const float* __restrict__ A, const float* __restrict__ W,
               float* __restrict__ C, int M, int N, int K,
               int bx, int by) {
    __shared__ uint32_t AF[2][AF_SZ];
    __shared__ uint32_t BF[2][BF_SZ];

    const int m0 = by * BM;
    const int n0 = bx * BN;
    const int tid = threadIdx.x;
    const int wid = tid >> 5;
    const int lane = tid & 31;
    const int qr = lane >> 2;
    const int ql = lane & 3;

    const int wm0 = (wid & 1) * 64;
    const int wn0 = (wid >> 1) * 64;

    const int grow = tid >> 2;
    const int c40  = (tid & 3) << 2;
    const int lf0  = (c40 & 7) >> 1;

    float acc[4][8][4];
#pragma unroll
    for (int mt = 0; mt < 4; ++mt)
#pragma unroll
        for (int nt = 0; nt < 8; ++nt)
#pragma unroll
            for (int i = 0; i < 4; ++i) acc[mt][nt][i] = 0.f;

    const int NT = K / 16;

    auto stA = [&](int buf, int r, float4 v) {
        const int reg  = ((c40 & 8) ? 2 : 0) + (((r & 15) >= 8) ? 1 : 0);
        const int base = (r >> 4) * AF_SB + ((r & 7) * 4 + lf0) * 4 + reg;
        AF[buf][base    ] = packh2(v.x, v.y);
        AF[buf][base + 4] = packh2(v.z, v.w);
    };
    auto stB = [&](int buf, int r, float4 v) {
        const int reg  = (c40 & 8) ? 1 : 0;
        const int base = (r >> 3) * BF_SB + ((r & 7) * 4 + lf0) * 2 + reg;
        BF[buf][base    ] = packh2(v.x, v.y);
        BF[buf][base + 2] = packh2(v.z, v.w);
    };

#pragma unroll
    for (int it = 0; it < 2; ++it) {
        int r = grow + it * 64;
        stA(0, r, *(const float4*)(A + (size_t)(m0 + r) * K + c40));
    }
#pragma unroll
    for (int it = 0; it < 4; ++it) {
        int r = grow + it * 64;
        stB(0, r, *(const float4*)(W + (size_t)(n0 + r) * K + c40));
    }
    __syncthreads();

    for (int kt = 0; kt < NT; ++kt) {
        const int cur = kt & 1;

        float4 pa[2], pb[4];
        if (kt + 1 < NT) {
            const int k0 = (kt + 1) * 16;
#pragma unroll
            for (int it = 0; it < 2; ++it) {
                int r = grow + it * 64;
                pa[it] = *(const float4*)(A + (size_t)(m0 + r) * K + k0 + c40);
            }
#pragma unroll
            for (int it = 0; it < 4; ++it) {
                int r = grow + it * 64;
                pb[it] = *(const float4*)(W + (size_t)(n0 + r) * K + k0 + c40);
            }
        }

        {
            uint4 av[4];
            uint2 bv[8];
#pragma unroll
            for (int mt = 0; mt < 4; ++mt)
                av[mt] = *(const uint4*)&AF[cur][(((wm0 >> 4) + mt)) * AF_SB + lane * 4];
#pragma unroll
            for (int nt = 0; nt < 8; ++nt)
                bv[nt] = *(const uint2*)&BF[cur][(((wn0 >> 3) + nt)) * BF_SB + lane * 2];
#pragma unroll
            for (int mt = 0; mt < 4; ++mt)
#pragma unroll
                for (int nt = 0; nt < 8; ++nt)
                    mma_f16(acc[mt][nt], (const uint32_t*)&av[mt],
                            (const uint32_t*)&bv[nt]);
        }

        if (kt + 1 < NT) {
            const int nxt = cur ^ 1;
#pragma unroll
            for (int it = 0; it < 2; ++it) stA(nxt, grow + it * 64, pa[it]);
#pragma unroll
            for (int it = 0; it < 4; ++it) stB(nxt, grow + it * 64, pb[it]);
            __syncthreads();
        }
    }

#pragma unroll
    for (int mt = 0; mt < 4; ++mt) {
#pragma unroll
        for (int nt = 0; nt < 8; ++nt) {
#pragma unroll
            for (int half = 0; half < 2; ++half) {
                int m = m0 + wm0 + mt * 16 + qr + half * 8;
                int n = n0 + wn0 + nt * 8 + ql * 2;
                float* p;
                if (MODE == 0) {
                    p = C + (size_t)m * N + n;
                } else {
                    int b  = m >> 11;
                    int s  = m & (S_ - 1);
                    int h  = n >> 6;
                    int dk = n & 63;
                    p = C + ((size_t)((b * H_ + h) * S_ + s)) * DK_ + dk;
                }
                *(float2*)p = make_float2(acc[mt][nt][half * 2],
                                          acc[mt][nt][half * 2 + 1]);
            }
        }
    }
}

__global__ __launch_bounds__(256, 1)
void gemm_qkv(const float* __restrict__ q, const float* __restrict__ k,
              const float* __restrict__ v,
              const float* __restrict__ Wq, const float* __restrict__ Wk,
              const float* __restrict__ Wv,
              float* __restrict__ Qo, float* __restrict__ Ko,
              float* __restrict__ Vo) {
    const float* A = (blockIdx.z == 0) ? q  : (blockIdx.z == 1) ? k  : v;
    const float* W = (blockIdx.z == 0) ? Wq : (blockIdx.z == 1) ? Wk : Wv;
    float*       C = (blockIdx.z == 0) ? Qo : (blockIdx.z == 1) ? Ko : Vo;
    gemm_core<1>(A, W, C, M_, D_, D_, blockIdx.x, blockIdx.y);
}

__global__ __launch_bounds__(256, 1)
void gemm_out(const float* __restrict__ A, const float* __restrict__ W,
              float* __restrict__ C) {
    gemm_core<0>(A, W, C, M_, D_, D_, blockIdx.x, blockIdx.y);
}

// ============================================================================
// Flash attention, FP16 m16n8k16, causal. 64 q-rows/block, 128 thr (4 warps
// x 16 rows). Fragment-major smem for Q/K/V; P stays in registers (the QK^T
// c-frag IS the PV a-frag after half2 packing). 2 barriers per tile.
// Q/K staging = GEMM stA/stB formulas (validated R13). V staged with 16-bit
// scatter stores (k runs along the half2 axis for the B fragment).
// ============================================================================
#define QSUB 16   // 4 rowblocks * 4 ksteps
#define KSUB 32   // 8 nblocks * 4 ksteps
#define VSUB 32   // 8 dkblocks * 4 ksteps

__global__ __launch_bounds__(128)
void attn_mma(const float* __restrict__ Q, const float* __restrict__ K,
              const float* __restrict__ V, float* __restrict__ Out) {
    __shared__ uint32_t sQ[QSUB * AF_SB];   // 2112 words
    __shared__ uint32_t sK[KSUB * BF_SB];   // 2112
    __shared__ uint32_t sV[VSUB * BF_SB];   // 2112

    const int qt  = blockIdx.x;
    const int bh  = blockIdx.y;
    const int tid = threadIdx.x;
    const int wid = tid >> 5;
    const int lane = tid & 31;
    const int qr = lane >> 2;
    const int ql = lane & 3;
    const int wm = wid * 16;

    // ---- Load Q tile once, fragment-major fp16 ----
    {
        const float* Qg = Q + ((size_t)bh * S_ + qt * 64) * DK_;
#pragma unroll
        for (int it = 0; it < 8; ++it) {
            int f = tid + it * 128;          // 0..1023
            int row = f >> 4;                // 0..63
            int c4  = (f & 15) << 2;         // 0..60
            float4 v = *(const float4*)(Qg + row * 64 + c4);
            const int ks = c4 >> 4;
            const int kk = c4 & 15;
            const int reg  = ((kk & 8) ? 2 : 0) + (((row & 15) >= 8) ? 1 : 0);
            const int base = ((row >> 4) * 4 + ks) * AF_SB
                           + ((row & 7) * 4 + ((kk & 7) >> 1)) * 4 + reg;
            sQ[base    ] = packh2(v.x, v.y);
            sQ[base + 4] = packh2(v.z, v.w);
        }
    }

    float mrow0 = -1e30f, mrow1 = -1e30f, lrow0 = 0.f, lrow1 = 0.f;
    float o[8][4];
#pragma unroll
    for (int nt = 0; nt < 8; ++nt)
#pragma unroll
        for (int e = 0; e < 4; ++e) o[nt][e] = 0.f;

    for (int t = 0; t <= qt; ++t) {
        __syncthreads();   // prev-iter K/V readers done (t=0: Q-store visibility)

        // ---- Stage K (fragment-major b32) and V (half scatter) ----
        const float* Kg = K + ((size_t)bh * S_ + t * 64) * DK_;
        const float* Vg = V + ((size_t)bh * S_ + t * 64) * DK_;
#pragma unroll
        for (int it = 0; it < 8; ++it) {
            int f = tid + it * 128;
            int row = f >> 4;                // K: n (kv row); V: k (kv pos)
            int c4  = (f & 15) << 2;         // K: k (dk);     V: dk
            const int ks = c4 >> 4;
            const int kk = c4 & 15;
            float4 kv4 = *(const float4*)(Kg + row * 64 + c4);
            {
                const int reg  = (kk & 8) ? 1 : 0;
                const int base = ((row >> 3) * 4 + ks) * BF_SB
                               + ((row & 7) * 4 + ((kk & 7) >> 1)) * 2 + reg;
                sK[base    ] = packh2(kv4.x, kv4.y);
                sK[base + 2] = packh2(kv4.z, kv4.w);
            }
            float4 vv4 = *(const float4*)(Vg + row * 64 + c4);
            {
                // V element (k=row, n=dk=c4+j): kstep along row
                const int vks  = row >> 4;
                const int vkk  = row & 15;
                const int vreg = (vkk & 8) ? 1 : 0;
                const int voff = ((vkk & 7) >> 1);
                const int hsel = vkk & 1;
                __half* hv = (__half*)sV;
#pragma unroll
                for (int j = 0; j < 4; ++j) {
                    const int dk = c4 + j;
                    const int word = (((dk >> 3) * 4 + vks)) * BF_SB
                                   + ((dk & 7) * 4 + voff) * 2 + vreg;
                    float comp = (j == 0) ? vv4.x : (j == 1) ? vv4.y
                               : (j == 2) ? vv4.z : vv4.w;
                    hv[word * 2 + hsel] = __float2half(comp);
                }
            }
        }
        __syncthreads();

        // ---- QK^T: 16x64 per warp, fp16 k16 ----
        float sc[8][4];
#pragma unroll
        for (int nt = 0; nt < 8; ++nt)
#pragma unroll
            for (int e = 0; e < 4; ++e) sc[nt][e] = 0.f;

#pragma unroll
        for (int ks = 0; ks < 4; ++ks) {
            uint4 a = *(const uint4*)&sQ[((wm >> 4) * 4 + ks) * AF_SB + lane * 4];
#pragma unroll
            for (int nt = 0; nt < 8; ++nt) {
                uint2 b = *(const uint2*)&sK[(nt * 4 + ks) * BF_SB + lane * 2];
                mma_f16(sc[nt], (const uint32_t*)&a, (const uint32_t*)&b);
            }
        }

        // ---- scale + causal mask + online softmax (registers only) ----
        const int r0l = wm + qr, r1l = wm + qr + 8;
        float tm0 = -1e30f, tm1 = -1e30f;
#pragma unroll
        for (int nt = 0; nt < 8; ++nt) {
            const int c0 = nt * 8 + 2 * ql, c1 = c0 + 1;
#pragma unroll
            for (int e = 0; e < 4; ++e) sc[nt][e] *= 0.125f;
            if (t == qt) {
                if (c0 > r0l) sc[nt][0] = -1e9f;
                if (c1 > r0l) sc[nt][1] = -1e9f;
                if (c0 > r1l) sc[nt][2] = -1e9f;
                if (c1 > r1l) sc[nt][3] = -1e9f;
            }
            tm0 = fmaxf(tm0, fmaxf(sc[nt][0], sc[nt][1]));
            tm1 = fmaxf(tm1, fmaxf(sc[nt][2], sc[nt][3]));
        }
        tm0 = fmaxf(tm0, __shfl_xor_sync(0xffffffffu, tm0, 1));
        tm0 = fmaxf(tm0, __shfl_xor_sync(0xffffffffu, tm0, 2));
        tm1 = fmaxf(tm1, __shfl_xor_sync(0xffffffffu, tm1, 1));
        tm1 = fmaxf(tm1, __shfl_xor_sync(0xffffffffu, tm1, 2));

        const float nm0 = fmaxf(mrow0, tm0);
        const float nm1 = fmaxf(mrow1, tm1);
        const float al0 = __expf(mrow0 - nm0);
        const float al1 = __expf(mrow1 - nm1);
        float sum0 = 0.f, sum1 = 0.f;
#pragma unroll
        for (int nt = 0; nt < 8; ++nt) {
            sc[nt][0] = __expf(sc[nt][0] - nm0);
            sc[nt][1] = __expf(sc[nt][1] - nm0);
            sc[nt][2] = __expf(sc[nt][2] - nm1);
            sc[nt][3] = __expf(sc[nt][3] - nm1);
            sum0 += sc[nt][0] + sc[nt][1];
            sum1 += sc[nt][2] + sc[nt][3];
        }
        sum0 += __shfl_xor_sync(0xffffffffu, sum0, 1);
        sum0 += __shfl_xor_sync(0xffffffffu, sum0, 2);
        sum1 += __shfl_xor_sync(0xffffffffu, sum1, 1);
        sum1 += __shfl_xor_sync(0xffffffffu, sum1, 2);

        lrow0 = lrow0 * al0 + sum0;
        lrow1 = lrow1 * al1 + sum1;
        mrow0 = nm0; mrow1 = nm1;

#pragma unroll
        for (int nt = 0; nt < 8; ++nt) {
            o[nt][0] *= al0; o[nt][1] *= al0;
            o[nt][2] *= al1; o[nt][3] *= al1;
        }

        // ---- PV: O += P @ V. P c-frag == fp16 a-frag after packing. ----
#pragma unroll
        for (int ks = 0; ks < 4; ++ks) {
            uint32_t ap[4];
            ap[0] = packh2(sc[2 * ks    ][0], sc[2 * ks    ][1]);
            ap[1] = packh2(sc[2 * ks    ][2], sc[2 * ks    ][3]);
            ap[2] = packh2(sc[2 * ks + 1][0], sc[2 * ks + 1][1]);
            ap[3] = packh2(sc[2 * ks + 1][2], sc[2 * ks + 1][3]);
#pragma unroll
            for (int nt = 0; nt < 8; ++nt) {
                uint2 b = *(const uint2*)&sV[(nt * 4 + ks) * BF_SB + lane * 2];
                mma_f16(o[nt], ap, (const uint32_t*)&b);
            }
        }
    }

    // Epilogue -> [B,S,D]
    const float i0 = 1.f / lrow0, i1 = 1.f / lrow1;
    const int b = bh >> 4, h = bh & 15;
    const int s0 = qt * 64 + wm + qr, s1 = s0 + 8;
#pragma unroll
    for (int nt = 0; nt < 8; ++nt) {
        const int dk = nt * 8 + 2 * ql;
        float* p0 = Out + ((size_t)(b * S_ + s0)) * D_ + h * DK_ + dk;
        *(float2*)p0 = make_float2(o[nt][0] * i0, o[nt][1] * i0);
        float* p1 = Out + ((size_t)(b * S_ + s1)) * D_ + h * DK_ + dk;
        *(float2*)p1 = make_float2(o[nt][2] * i1, o[nt][3] * i1);
    }
}

// ============================================================================
// Launch
// ============================================================================
extern "C" void kernel_launch(void* const* d_in, const int* in_sizes, int n_in,
                              void* d_out, int out_size) {
    const float* q  = (const float*)d_in[0];
    const float* k  = (const float*)d_in[1];
    const float* v  = (const float*)d_in[2];
    // d_in[3] = mask (causal, known statically) — unused
    const float* Wq = (const float*)d_in[4];
    const float* Wk = (const float*)d_in[5];
    const float* Wv = (const float*)d_in[6];
    const float* Wo = (const float*)d_in[7];
    float* out = (float*)d_out;

    float *pQ, *pK, *pV, *pA;
    cudaGetSymbolAddress((void**)&pQ, g_Q);
    cudaGetSymbolAddress((void**)&pK, g_K);
    cudaGetSymbolAddress((void**)&pV, g_V);
    cudaGetSymbolAddress((void**)&pA, g_A);

    dim3 qkv_grid(D_ / BN, M_ / BM, 3);   // (4, 64, 3)
    gemm_qkv<<<qkv_grid, 256>>>(q, k, v, Wq, Wk, Wv, pQ, pK, pV);

    attn_mma<<<dim3(S_ / 64, B_ * H_), 128>>>(pQ, pK, pV, pA);

    dim3 ogrid(D_ / BN, M_ / BM);         // (4, 64)
    gemm_out<<<ogrid, 256>>>(pA, Wo, out);
}

// round 15
// speedup vs baseline: 1.5527x; 1.0789x over previous
#include <cuda_runtime.h>
#include <cuda_fp16.h>
#include <cstdint>

// Problem constants
#define B_  4
#define S_  2048
#define D_  1024
#define H_  16
#define DK_ 64
#define M_  (B_*S_)   // 8192

// Scratch (device globals — no allocations allowed)
__device__ float g_Q[(size_t)B_*H_*S_*DK_];
__device__ float g_K[(size_t)B_*H_*S_*DK_];
__device__ float g_V[(size_t)B_*H_*S_*DK_];
__device__ float g_A[(size_t)B_*S_*D_];

__device__ __forceinline__ uint32_t packh2(float x, float y) {
    __half2 h = __floats2half2_rn(x, y);
    return *(uint32_t*)&h;
}

__device__ __forceinline__ void mma_f16(float d[4], const uint32_t a[4],
                                        const uint32_t b[2]) {
    asm volatile(
        "mma.sync.aligned.m16n8k16.row.col.f32.f16.f16.f32 "
        "{%0,%1,%2,%3}, {%4,%5,%6,%7}, {%8,%9}, {%0,%1,%2,%3};\n"
        : "+f"(d[0]), "+f"(d[1]), "+f"(d[2]), "+f"(d[3])
        : "r"(a[0]), "r"(a[1]), "r"(a[2]), "r"(a[3]),
          "r"(b[0]), "r"(b[1]));
}

// ============================================================================
// FP16 tensor-core GEMM (m16n8k16), FRAGMENT-MAJOR static smem: C = A @ W^T.
// Block 128x128, BK=16, 256 thr, 8 warps of 64x32 -> acc 64 regs/thread,
// 2 CTAs/SM (launch_bounds(256,2)) for cross-CTA latency hiding.
// Fragment positions (validated R13):
//   A: sub (r/16): b32 idx = lane*4 + reg, reg=(k>=8)*2+(r%16>=8),
//      lane=(r%8)*4+(k%8)/2. Sub stride 132 -> LDS.128 consumer.
//   W: sub (n/8):  b32 idx = lane*2 + reg, reg=(k>=8),
//      lane=(n%8)*4+(k%8)/2. Sub stride 66 -> LDS.64 consumer.
// MODE 0: C row-major [M,N]. MODE 1: split-heads epilogue.
// ============================================================================
#define BM 128
#define BN 128
#define AF_SB 132
#define BF_SB 66
#define AF_SZ (8 * AF_SB)     // 1056 b32 per buffer (8 mrow-blocks)
#define BF_SZ (16 * BF_SB)    // 1056 b32 per buffer (16 nrow-blocks)

template<int MODE>
__device__ __forceinline__
void gemm_core(const float* __restrict__ A, const float* __restrict__ W,
               float* __restrict__ C, int M, int N, int K,
               int bx, int by) {
    __shared__ uint32_t AF[2][AF_SZ];
    __shared__ uint32_t BF[2][BF_SZ];

    const int m0 = by * BM;
    const int n0 = bx * BN;
    const int tid = threadIdx.x;
    const int wid = tid >> 5;
    const int lane = tid & 31;
    const int qr = lane >> 2;
    const int ql = lane & 3;

    const int wm0 = (wid & 1) * 64;    // warp m-origin (2 slots)
    const int wn0 = (wid >> 1) * 32;   // warp n-origin (4 slots)

    const int grow = tid >> 2;             // 0..63
    const int c40  = (tid & 3) << 2;       // 0,4,8,12
    const int lf0  = (c40 & 7) >> 1;

    float acc[4][4][4];
#pragma unroll
    for (int mt = 0; mt < 4; ++mt)
#pragma unroll
        for (int nt = 0; nt < 4; ++nt)
#pragma unroll
            for (int i = 0; i < 4; ++i) acc[mt][nt][i] = 0.f;

    const int NT = K / 16;

    auto stA = [&](int buf, int r, float4 v) {
        const int reg  = ((c40 & 8) ? 2 : 0) + (((r & 15) >= 8) ? 1 : 0);
        const int base = (r >> 4) * AF_SB + ((r & 7) * 4 + lf0) * 4 + reg;
        AF[buf][base    ] = packh2(v.x, v.y);
        AF[buf][base + 4] = packh2(v.z, v.w);
    };
    auto stB = [&](int buf, int r, float4 v) {
        const int reg  = (c40 & 8) ? 1 : 0;
        const int base = (r >> 3) * BF_SB + ((r & 7) * 4 + lf0) * 2 + reg;
        BF[buf][base    ] = packh2(v.x, v.y);
        BF[buf][base + 2] = packh2(v.z, v.w);
    };

    // Prologue: stage tile 0 (A and W both 128 rows)
#pragma unroll
    for (int it = 0; it < 2; ++it) {
        int r = grow + it * 64;
        stA(0, r, *(const float4*)(A + (size_t)(m0 + r) * K + c40));
        stB(0, r, *(const float4*)(W + (size_t)(n0 + r) * K + c40));
    }
    __syncthreads();

    for (int kt = 0; kt < NT; ++kt) {
        const int cur = kt & 1;

        // Prefetch next tile gmem -> regs
        float4 pa[2], pb[2];
        if (kt + 1 < NT) {
            const int k0 = (kt + 1) * 16;
#pragma unroll
            for (int it = 0; it < 2; ++it) {
                int r = grow + it * 64;
                pa[it] = *(const float4*)(A + (size_t)(m0 + r) * K + k0 + c40);
                pb[it] = *(const float4*)(W + (size_t)(n0 + r) * K + k0 + c40);
            }
        }

        // Compute: one k16 step, 16 MMAs/warp
        {
            uint4 av[4];
            uint2 bv[4];
#pragma unroll
            for (int mt = 0; mt < 4; ++mt)
                av[mt] = *(const uint4*)&AF[cur][((wm0 >> 4) + mt) * AF_SB + lane * 4];
#pragma unroll
            for (int nt = 0; nt < 4; ++nt)
                bv[nt] = *(const uint2*)&BF[cur][((wn0 >> 3) + nt) * BF_SB + lane * 2];
#pragma unroll
            for (int mt = 0; mt < 4; ++mt)
#pragma unroll
                for (int nt = 0; nt < 4; ++nt)
                    mma_f16(acc[mt][nt], (const uint32_t*)&av[mt],
                            (const uint32_t*)&bv[nt]);
        }

        // Store prefetched tile to the other buffer
        if (kt + 1 < NT) {
            const int nxt = cur ^ 1;
#pragma unroll
            for (int it = 0; it < 2; ++it) {
                stA(nxt, grow + it * 64, pa[it]);
                stB(nxt, grow + it * 64, pb[it]);
            }
            __syncthreads();
        }
    }

    // Epilogue (c-frag: c0,c1 @(row,col..col+1); c2,c3 @(row+8,...))
#pragma unroll
    for (int mt = 0; mt < 4; ++mt) {
#pragma unroll
        for (int nt = 0; nt < 4; ++nt) {
#pragma unroll
            for (int half = 0; half < 2; ++half) {
                int m = m0 + wm0 + mt * 16 + qr + half * 8;
                int n = n0 + wn0 + nt * 8 + ql * 2;
                float* p;
                if (MODE == 0) {
                    p = C + (size_t)m * N + n;
                } else {
                    int b  = m >> 11;
                    int s  = m & (S_ - 1);
                    int h  = n >> 6;
                    int dk = n & 63;
                    p = C + ((size_t)((b * H_ + h) * S_ + s)) * DK_ + dk;
                }
                *(float2*)p = make_float2(acc[mt][nt][half * 2],
                                          acc[mt][nt][half * 2 + 1]);
            }
        }
    }
}

__global__ __launch_bounds__(256, 2)
void gemm_qkv(const float* __restrict__ q, const float* __restrict__ k,
              const float* __restrict__ v,
              const float* __restrict__ Wq, const float* __restrict__ Wk,
              const float* __restrict__ Wv,
              float* __restrict__ Qo, float* __restrict__ Ko,
              float* __restrict__ Vo) {
    const float* A = (blockIdx.z == 0) ? q  : (blockIdx.z == 1) ? k  : v;
    const float* W = (blockIdx.z == 0) ? Wq : (blockIdx.z == 1) ? Wk : Wv;
    float*       C = (blockIdx.z == 0) ? Qo : (blockIdx.z == 1) ? Ko : Vo;
    gemm_core<1>(A, W, C, M_, D_, D_, blockIdx.x, blockIdx.y);
}

__global__ __launch_bounds__(256, 2)
void gemm_out(const float* __restrict__ A, const float* __restrict__ W,
              float* __restrict__ C) {
    gemm_core<0>(A, W, C, M_, D_, D_, blockIdx.x, blockIdx.y);
}

// ============================================================================
// Flash attention, FP16 m16n8k16, causal (unchanged from passing R14 kernel).
// 64 q-rows/block, 128 thr (4 warps x 16 rows). P stays in registers.
// ============================================================================
#define QSUB 16
#define KSUB 32
#define VSUB 32

__global__ __launch_bounds__(128)
void attn_mma(const float* __restrict__ Q, const float* __restrict__ K,
              const float* __restrict__ V, float* __restrict__ Out) {
    __shared__ uint32_t sQ[QSUB * AF_SB];
    __shared__ uint32_t sK[KSUB * BF_SB];
    __shared__ uint32_t sV[VSUB * BF_SB];

    const int qt  = blockIdx.x;
    const int bh  = blockIdx.y;
    const int tid = threadIdx.x;
    const int wid = tid >> 5;
    const int lane = tid & 31;
    const int qr = lane >> 2;
    const int ql = lane & 3;
    const int wm = wid * 16;

    // ---- Load Q tile once, fragment-major fp16 ----
    {
        const float* Qg = Q + ((size_t)bh * S_ + qt * 64) * DK_;
#pragma unroll
        for (int it = 0; it < 8; ++it) {
            int f = tid + it * 128;
            int row = f >> 4;
            int c4  = (f & 15) << 2;
            float4 v = *(const float4*)(Qg + row * 64 + c4);
            const int ks = c4 >> 4;
            const int kk = c4 & 15;
            const int reg  = ((kk & 8) ? 2 : 0) + (((row & 15) >= 8) ? 1 : 0);
            const int base = ((row >> 4) * 4 + ks) * AF_SB
                           + ((row & 7) * 4 + ((kk & 7) >> 1)) * 4 + reg;
            sQ[base    ] = packh2(v.x, v.y);
            sQ[base + 4] = packh2(v.z, v.w);
        }
    }

    float mrow0 = -1e30f, mrow1 = -1e30f, lrow0 = 0.f, lrow1 = 0.f;
    float o[8][4];
#pragma unroll
    for (int nt = 0; nt < 8; ++nt)
#pragma unroll
        for (int e = 0; e < 4; ++e) o[nt][e] = 0.f;

    for (int t = 0; t <= qt; ++t) {
        __syncthreads();

        const float* Kg = K + ((size_t)bh * S_ + t * 64) * DK_;
        const float* Vg = V + ((size_t)bh * S_ + t * 64) * DK_;
#pragma unroll
        for (int it = 0; it < 8; ++it) {
            int f = tid + it * 128;
            int row = f >> 4;
            int c4  = (f & 15) << 2;
            const int ks = c4 >> 4;
            const int kk = c4 & 15;
            float4 kv4 = *(const float4*)(Kg + row * 64 + c4);
            {
                const int reg  = (kk & 8) ? 1 : 0;
                const int base = ((row >> 3) * 4 + ks) * BF_SB
                               + ((row & 7) * 4 + ((kk & 7) >> 1)) * 2 + reg;
                sK[base    ] = packh2(kv4.x, kv4.y);
                sK[base + 2] = packh2(kv4.z, kv4.w);
            }
            float4 vv4 = *(const float4*)(Vg + row * 64 + c4);
            {
                const int vks  = row >> 4;
                const int vkk  = row & 15;
                const int vreg = (vkk & 8) ? 1 : 0;
                const int voff = ((vkk & 7) >> 1);
                const int hsel = vkk & 1;
                __half* hv = (__half*)sV;
#pragma unroll
                for (int j = 0; j < 4; ++j) {
                    const int dk = c4 + j;
                    const int word = (((dk >> 3) * 4 + vks)) * BF_SB
                                   + ((dk & 7) * 4 + voff) * 2 + vreg;
                    float comp = (j == 0) ? vv4.x : (j == 1) ? vv4.y
                               : (j == 2) ? vv4.z : vv4.w;
                    hv[word * 2 + hsel] = __float2half(comp);
                }
            }
        }
        __syncthreads();

        // ---- QK^T ----
        float sc[8][4];
#pragma unroll
        for (int nt = 0; nt < 8; ++nt)
#pragma unroll
            for (int e = 0; e < 4; ++e) sc[nt][e] = 0.f;

#pragma unroll
        for (int ks = 0; ks < 4; ++ks) {
            uint4 a = *(const uint4*)&sQ[((wm >> 4) * 4 + ks) * AF_SB + lane * 4];
#pragma unroll
            for (int nt = 0; nt < 8; ++nt) {
                uint2 b = *(const uint2*)&sK[(nt * 4 + ks) * BF_SB + lane * 2];
                mma_f16(sc[nt], (const uint32_t*)&a, (const uint32_t*)&b);
            }
        }

        // ---- scale + causal mask + online softmax ----
        const int r0l = wm + qr, r1l = wm + qr + 8;
        float tm0 = -1e30f, tm1 = -1e30f;
#pragma unroll
        for (int nt = 0; nt < 8; ++nt) {
            const int c0 = nt * 8 + 2 * ql, c1 = c0 + 1;
#pragma unroll
            for (int e = 0; e < 4; ++e) sc[nt][e] *= 0.125f;
            if (t == qt) {
                if (c0 > r0l) sc[nt][0] = -1e9f;
                if (c1 > r0l) sc[nt][1] = -1e9f;
                if (c0 > r1l) sc[nt][2] = -1e9f;
                if (c1 > r1l) sc[nt][3] = -1e9f;
            }
            tm0 = fmaxf(tm0, fmaxf(sc[nt][0], sc[nt][1]));
            tm1 = fmaxf(tm1, fmaxf(sc[nt][2], sc[nt][3]));
        }
        tm0 = fmaxf(tm0, __shfl_xor_sync(0xffffffffu, tm0, 1));
        tm0 = fmaxf(tm0, __shfl_xor_sync(0xffffffffu, tm0, 2));
        tm1 = fmaxf(tm1, __shfl_xor_sync(0xffffffffu, tm1, 1));
        tm1 = fmaxf(tm1, __shfl_xor_sync(0xffffffffu, tm1, 2));

        const float nm0 = fmaxf(mrow0, tm0);
        const float nm1 = fmaxf(mrow1, tm1);
        const float al0 = __expf(mrow0 - nm0);
        const float al1 = __expf(mrow1 - nm1);
        float sum0 = 0.f, sum1 = 0.f;
#pragma unroll
        for (int nt = 0; nt < 8; ++nt) {
            sc[nt][0] = __expf(sc[nt][0] - nm0);
            sc[nt][1] = __expf(sc[nt][1] - nm0);
            sc[nt][2] = __expf(sc[nt][2] - nm1);
            sc[nt][3] = __expf(sc[nt][3] - nm1);
            sum0 += sc[nt][0] + sc[nt][1];
            sum1 += sc[nt][2] + sc[nt][3];
        }
        sum0 += __shfl_xor_sync(0xffffffffu, sum0, 1);
        sum0 += __shfl_xor_sync(0xffffffffu, sum0, 2);
        sum1 += __shfl_xor_sync(0xffffffffu, sum1, 1);
        sum1 += __shfl_xor_sync(0xffffffffu, sum1, 2);

        lrow0 = lrow0 * al0 + sum0;
        lrow1 = lrow1 * al1 + sum1;
        mrow0 = nm0; mrow1 = nm1;

#pragma unroll
        for (int nt = 0; nt < 8; ++nt) {
            o[nt][0] *= al0; o[nt][1] *= al0;
            o[nt][2] *= al1; o[nt][3] *= al1;
        }

        // ---- PV: P c-frag == fp16 a-frag after packing ----
#pragma unroll
        for (int ks = 0; ks < 4; ++ks) {
            uint32_t ap[4];
            ap[0] = packh2(sc[2 * ks    ][0], sc[2 * ks    ][1]);
            ap[1] = packh2(sc[2 * ks    ][2], sc[2 * ks    ][3]);
            ap[2] = packh2(sc[2 * ks + 1][0], sc[2 * ks + 1][1]);
            ap[3] = packh2(sc[2 * ks + 1][2], sc[2 * ks + 1][3]);
#pragma unroll
            for (int nt = 0; nt < 8; ++nt) {
                uint2 b = *(const uint2*)&sV[(nt * 4 + ks) * BF_SB + lane * 2];
                mma_f16(o[nt], ap, (const uint32_t*)&b);
            }
        }
    }

    // Epilogue -> [B,S,D]
    const float i0 = 1.f / lrow0, i1 = 1.f / lrow1;
    const int b = bh >> 4, h = bh & 15;
    const int s0 = qt * 64 + wm + qr, s1 = s0 + 8;
#pragma unroll
    for (int nt = 0; nt < 8; ++nt) {
        const int dk = nt * 8 + 2 * ql;
        float* p0 = Out + ((size_t)(b * S_ + s0)) * D_ + h * DK_ + dk;
        *(float2*)p0 = make_float2(o[nt][0] * i0, o[nt][1] * i0);
        float* p1 = Out + ((size_t)(b * S_ + s1)) * D_ + h * DK_ + dk;
        *(float2*)p1 = make_float2(o[nt][2] * i1, o[nt][3] * i1);
    }
}

// ============================================================================
// Launch
// ============================================================================
extern "C" void kernel_launch(void* const* d_in, const int* in_sizes, int n_in,
                              void* d_out, int out_size) {
    const float* q  = (const float*)d_in[0];
    const float* k  = (const float*)d_in[1];
    const float* v  = (const float*)d_in[2];
    // d_in[3] = mask (causal, known statically) — unused
    const float* Wq = (const float*)d_in[4];
    const float* Wk = (const float*)d_in[5];
    const float* Wv = (const float*)d_in[6];
    const float* Wo = (const float*)d_in[7];
    float* out = (float*)d_out;

    float *pQ, *pK, *pV, *pA;
    cudaGetSymbolAddress((void**)&pQ, g_Q);
    cudaGetSymbolAddress((void**)&pK, g_K);
    cudaGetSymbolAddress((void**)&pV, g_V);
    cudaGetSymbolAddress((void**)&pA, g_A);

    dim3 qkv_grid(D_ / BN, M_ / BM, 3);   // (8, 64, 3)
    gemm_qkv<<<qkv_grid, 256>>>(q, k, v, Wq, Wk, Wv, pQ, pK, pV);

    attn_mma<<<dim3(S_ / 64, B_ * H_), 128>>>(pQ, pK, pV, pA);

    dim3 ogrid(D_ / BN, M_ / BM);         // (8, 64)
    gemm_out<<<ogrid, 256>>>(pA, Wo, out);
}

// round 17
// speedup vs baseline: 1.9737x; 1.2712x over previous
#include <cuda_runtime.h>
#include <cuda_fp16.h>
#include <cstdint>

// Problem constants
#define B_  4
#define S_  2048
#define D_  1024
#define H_  16
#define DK_ 64
#define M_  (B_*S_)            // 8192
#define MD_ ((size_t)M_*D_)    // 8388608
#define DD_ ((size_t)D_*D_)    // 1048576

// fp16 scratch (device globals — no allocations allowed)
__device__ __half g_qh[MD_], g_kh[MD_], g_vh[MD_];   // fp16 inputs
__device__ __half g_wh[4*DD_];                        // fp16 weights (q,k,v,o)
__device__ __half g_Qh[MD_], g_Kh[MD_], g_Vh[MD_];   // fp16 projections [B,H,S,DK]
__device__ __half g_ah[MD_];                          // fp16 attention out [B,S,D]

__device__ __forceinline__ uint32_t packh2(float x, float y) {
    __half2 h = __floats2half2_rn(x, y);
    return *(uint32_t*)&h;
}
__device__ __forceinline__ uint32_t smem_u32(const void* p) {
    uint32_t a;
    asm("{ .reg .u64 t; cvta.to.shared.u64 t, %1; cvt.u32.u64 %0, t; }"
        : "=r"(a) : "l"(p));
    return a;
}
__device__ __forceinline__ void mma_f16(float d[4], const uint32_t a[4],
                                        const uint32_t b[2]) {
    asm volatile(
        "mma.sync.aligned.m16n8k16.row.col.f32.f16.f16.f32 "
        "{%0,%1,%2,%3}, {%4,%5,%6,%7}, {%8,%9}, {%0,%1,%2,%3};\n"
        : "+f"(d[0]), "+f"(d[1]), "+f"(d[2]), "+f"(d[3])
        : "r"(a[0]), "r"(a[1]), "r"(a[2]), "r"(a[3]),
          "r"(b[0]), "r"(b[1]));
}
__device__ __forceinline__ void ldsm_x4(uint32_t r[4], uint32_t addr) {
    asm volatile("ldmatrix.sync.aligned.m8n8.x4.shared.b16 {%0,%1,%2,%3}, [%4];"
                 : "=r"(r[0]), "=r"(r[1]), "=r"(r[2]), "=r"(r[3]) : "r"(addr));
}
__device__ __forceinline__ void ldsm_x2(uint32_t r[2], uint32_t addr) {
    asm volatile("ldmatrix.sync.aligned.m8n8.x2.shared.b16 {%0,%1}, [%2];"
                 : "=r"(r[0]), "=r"(r[1]) : "r"(addr));
}
__device__ __forceinline__ void cp16(uint32_t s, const void* g) {
    asm volatile("cp.async.cg.shared.global [%0], [%1], 16;\n" :: "r"(s), "l"(g));
}
__device__ __forceinline__ void cp_commit() {
    asm volatile("cp.async.commit_group;\n" ::: "memory");
}
template<int N_> __device__ __forceinline__ void cp_wait() {
    asm volatile("cp.async.wait_group %0;\n" :: "n"(N_) : "memory");
}

// ============================================================================
// Prepass: fp32 -> fp16 converts (inputs + weights)
// ============================================================================
__global__ __launch_bounds__(256) void cvt3(
    const float* __restrict__ q, const float* __restrict__ k,
    const float* __restrict__ v,
    __half* qh, __half* kh, __half* vh) {
    const int z = blockIdx.z;
    const float* s = (z == 0) ? q : (z == 1) ? k : v;
    __half* d = (z == 0) ? qh : (z == 1) ? kh : vh;
    size_t i = ((size_t)blockIdx.x * 256 + threadIdx.x) * 8;
    float4 x0 = *(const float4*)(s + i);
    float4 x1 = *(const float4*)(s + i + 4);
    uint4 o;
    o.x = packh2(x0.x, x0.y); o.y = packh2(x0.z, x0.w);
    o.z = packh2(x1.x, x1.y); o.w = packh2(x1.z, x1.w);
    *(uint4*)(d + i) = o;
}
__global__ __launch_bounds__(256) void cvtw(
    const float* __restrict__ w0, const float* __restrict__ w1,
    const float* __restrict__ w2, const float* __restrict__ w3,
    __half* wh) {
    const int z = blockIdx.z;
    const float* s = (z == 0) ? w0 : (z == 1) ? w1 : (z == 2) ? w2 : w3;
    size_t i = ((size_t)blockIdx.x * 256 + threadIdx.x) * 8;
    float4 x0 = *(const float4*)(s + i);
    float4 x1 = *(const float4*)(s + i + 4);
    uint4 o;
    o.x = packh2(x0.x, x0.y); o.y = packh2(x0.z, x0.w);
    o.z = packh2(x1.x, x1.y); o.w = packh2(x1.z, x1.w);
    *(uint4*)(wh + z * DD_ + i) = o;
}

// ============================================================================
// FP16 GEMM, cp.async 3-stage + ldmatrix: C = A @ W^T.
// A:[M,1024] fp16 rm, W:[N,1024] fp16 rm. Block 128x128, BK=32 (2 k16 steps),
// 256 thr, 8 warps of 64x32, 2 CTAs/SM. Smem rows 64B data + 16B pad (80B
// pitch -> ldmatrix conflict-free). 1 barrier per BK=32 tile.
// MODE 0: C fp32 row-major [M,1024]. MODE 1: C fp16 split-heads [B,H,S,64].
// ============================================================================
#define BM 128
#define BN 128
#define PAB 80                    // bytes per smem row
#define STG_BYTES (128 * PAB)     // 10240 per array
#define STAGE_BYTES (2 * STG_BYTES)
#define NSTG 3
#define GEMM_SMEM (NSTG * STAGE_BYTES)   // 61440

template<int MODE>
__device__ __forceinline__
void gemm_core(const __half* __restrict__ A, const __half* __restrict__ W,
               void* __restrict__ Cv, int bx, int by) {
    extern __shared__ char dsm[];
    const uint32_t sb = smem_u32(dsm);

    const int m0 = by * BM;
    const int n0 = bx * BN;
    const int tid = threadIdx.x;
    const int wid = tid >> 5;
    const int lane = tid & 31;
    const int qr = lane >> 2;
    const int ql = lane & 3;

    const int wm0 = (wid & 1) * 64;
    const int wn0 = (wid >> 1) * 32;

    // cp.async coords: thread t covers row t/2, segs (t%2)*2 .. +1 (16B each)
    const int crow = tid >> 1;
    const int cseg = (tid & 1) * 2;

    float acc[4][4][4];
#pragma unroll
    for (int mt = 0; mt < 4; ++mt)
#pragma unroll
        for (int nt = 0; nt < 4; ++nt)
#pragma unroll
            for (int i = 0; i < 4; ++i) acc[mt][nt][i] = 0.f;

    const int NT = 1024 / 32;   // 32 k-tiles

    auto issue = [&](int st, int kt) {
        const uint32_t ab = sb + (uint32_t)st * STAGE_BYTES;
        const uint32_t bb = ab + STG_BYTES;
        const int kh = kt * 32;
#pragma unroll
        for (int i = 0; i < 2; ++i) {
            int seg = cseg + i;
            cp16(ab + crow * PAB + seg * 16,
                 A + (size_t)(m0 + crow) * 1024 + kh + seg * 8);
            cp16(bb + crow * PAB + seg * 16,
                 W + (size_t)(n0 + crow) * 1024 + kh + seg * 8);
        }
    };

    issue(0, 0); cp_commit();
    issue(1, 1); cp_commit();

    for (int kt = 0; kt < NT; ++kt) {
        cp_wait<1>();
        __syncthreads();
        if (kt + 2 < NT) issue((kt + 2) % NSTG, kt + 2);
        cp_commit();

        const uint32_t ab = sb + (uint32_t)(kt % NSTG) * STAGE_BYTES;
        const uint32_t bb = ab + STG_BYTES;
#pragma unroll
        for (int ks = 0; ks < 2; ++ks) {
            uint32_t af[4][4], bf[4][2];
#pragma unroll
            for (int mt = 0; mt < 4; ++mt)
                ldsm_x4(af[mt], ab + (wm0 + mt * 16 + (lane & 15)) * PAB
                               + ks * 32 + (lane >> 4) * 16);
#pragma unroll
            for (int nt = 0; nt < 4; ++nt)
                ldsm_x2(bf[nt], bb + (wn0 + nt * 8 + (lane & 7)) * PAB
                               + ks * 32 + ((lane >> 3) & 1) * 16);
#pragma unroll
            for (int mt = 0; mt < 4; ++mt)
#pragma unroll
                for (int nt = 0; nt < 4; ++nt)
                    mma_f16(acc[mt][nt], af[mt], bf[nt]);
        }
    }

    // Epilogue
#pragma unroll
    for (int mt = 0; mt < 4; ++mt) {
#pragma unroll
        for (int nt = 0; nt < 4; ++nt) {
#pragma unroll
            for (int half = 0; half < 2; ++half) {
                int m = m0 + wm0 + mt * 16 + qr + half * 8;
                int n = n0 + wn0 + nt * 8 + ql * 2;
                if (MODE == 0) {
                    float* p = (float*)Cv + (size_t)m * 1024 + n;
                    *(float2*)p = make_float2(acc[mt][nt][half * 2],
                                              acc[mt][nt][half * 2 + 1]);
                } else {
                    int b  = m >> 11;
                    int s  = m & (S_ - 1);
                    int h  = n >> 6;
                    int dk = n & 63;
                    __half* p = (__half*)Cv
                              + ((size_t)((b * H_ + h) * S_ + s)) * DK_ + dk;
                    *(uint32_t*)p = packh2(acc[mt][nt][half * 2],
                                           acc[mt][nt][half * 2 + 1]);
                }
            }
        }
    }
}

__global__ __launch_bounds__(256, 2)
void gemm_qkv(const __half* __restrict__ qh, const __half* __restrict__ kh,
              const __half* __restrict__ vh, const __half* __restrict__ wh,
              __half* Qo, __half* Ko, __half* Vo) {
    const int z = blockIdx.z;
    const __half* A = (z == 0) ? qh : (z == 1) ? kh : vh;
    const __half* W = wh + (size_t)z * DD_;
    __half* C = (z == 0) ? Qo : (z == 1) ? Ko : Vo;
    gemm_core<1>(A, W, C, blockIdx.x, blockIdx.y);
}

__global__ __launch_bounds__(256, 2)
void gemm_out(const __half* __restrict__ A, const __half* __restrict__ W,
              float* __restrict__ C) {
    gemm_core<0>(A, W, C, blockIdx.x, blockIdx.y);
}

// ============================================================================
// Flash attention, FP16 m16n8k16, causal. fp16 in (Q/K/V [B,H,S,64]),
// fp16 out ([B,S,D]). 64 q-rows/block, 128 thr. P register-resident.
// Fragment-major smem (validated R14), staging from fp16 (no converts).
// ============================================================================
#define AF_SB 132
#define BF_SB 66
#define QSUB 16
#define KSUB 32
#define VSUB 32

__global__ __launch_bounds__(128)
void attn_mma(const __half* __restrict__ Q, const __half* __restrict__ K,
              const __half* __restrict__ V, __half* __restrict__ Out) {
    __shared__ uint32_t sQ[QSUB * AF_SB];
    __shared__ uint32_t sK[KSUB * BF_SB];
    __shared__ uint32_t sV[VSUB * BF_SB];

    const int qt  = blockIdx.x;
    const int bh  = blockIdx.y;
    const int tid = threadIdx.x;
    const int wid = tid >> 5;
    const int lane = tid & 31;
    const int qr = lane >> 2;
    const int ql = lane & 3;
    const int wm = wid * 16;

    // ---- Q tile once: fp16 uint4 (8 halfs) -> A-frag positions ----
    {
        const __half* Qg = Q + ((size_t)bh * S_ + qt * 64) * DK_;
#pragma unroll
        for (int it = 0; it < 4; ++it) {
            int f = tid + it * 128;          // 0..511
            int row = f >> 3;                // 0..63
            int c8  = (f & 7) * 8;           // 0..56
            uint4 w = *(const uint4*)(Qg + row * 64 + c8);
            const int ks = c8 >> 4;
            const int kk = c8 & 15;          // 0 or 8
            const int reg  = ((kk & 8) ? 2 : 0) + (((row & 15) >= 8) ? 1 : 0);
            const int base = ((row >> 4) * 4 + ks) * AF_SB
                           + ((row & 7) * 4) * 4 + reg;
            sQ[base     ] = w.x; sQ[base +  4] = w.y;
            sQ[base +  8] = w.z; sQ[base + 12] = w.w;
        }
    }

    float mrow0 = -1e30f, mrow1 = -1e30f, lrow0 = 0.f, lrow1 = 0.f;
    float o[8][4];
#pragma unroll
    for (int nt = 0; nt < 8; ++nt)
#pragma unroll
        for (int e = 0; e < 4; ++e) o[nt][e] = 0.f;

    for (int t = 0; t <= qt; ++t) {
        __syncthreads();

        const __half* Kg = K + ((size_t)bh * S_ + t * 64) * DK_;
        const __half* Vg = V + ((size_t)bh * S_ + t * 64) * DK_;
#pragma unroll
        for (int it = 0; it < 4; ++it) {
            int f = tid + it * 128;
            int row = f >> 3;
            int c8  = (f & 7) * 8;
            const int ks = c8 >> 4;
            const int kk = c8 & 15;
            uint4 kw = *(const uint4*)(Kg + row * 64 + c8);
            {
                const int reg  = (kk & 8) ? 1 : 0;
                const int base = ((row >> 3) * 4 + ks) * BF_SB
                               + ((row & 7) * 4) * 2 + reg;
                sK[base    ] = kw.x; sK[base + 2] = kw.y;
                sK[base + 4] = kw.z; sK[base + 6] = kw.w;
            }
            uint4 vw = *(const uint4*)(Vg + row * 64 + c8);
            {
                const __half* v8 = (const __half*)&vw;
                const int vks  = row >> 4;
                const int vkk  = row & 15;
                const int vreg = (vkk & 8) ? 1 : 0;
                const int voff = ((vkk & 7) >> 1);
                const int hsel = vkk & 1;
                __half* hv = (__half*)sV;
#pragma unroll
                for (int j = 0; j < 8; ++j) {
                    const int dk = c8 + j;
                    const int word = (((dk >> 3) * 4 + vks)) * BF_SB
                                   + ((dk & 7) * 4 + voff) * 2 + vreg;
                    hv[word * 2 + hsel] = v8[j];
                }
            }
        }
        __syncthreads();

        // ---- QK^T ----
        float sc[8][4];
#pragma unroll
        for (int nt = 0; nt < 8; ++nt)
#pragma unroll
            for (int e = 0; e < 4; ++e) sc[nt][e] = 0.f;

#pragma unroll
        for (int ks = 0; ks < 4; ++ks) {
            uint4 a = *(const uint4*)&sQ[((wm >> 4) * 4 + ks) * AF_SB + lane * 4];
#pragma unroll
            for (int nt = 0; nt < 8; ++nt) {
                uint2 b = *(const uint2*)&sK[(nt * 4 + ks) * BF_SB + lane * 2];
                mma_f16(sc[nt], (const uint32_t*)&a, (const uint32_t*)&b);
            }
        }

        // ---- scale + causal mask + online softmax ----
        const int r0l = wm + qr, r1l = wm + qr + 8;
        float tm0 = -1e30f, tm1 = -1e30f;
#pragma unroll
        for (int nt = 0; nt < 8; ++nt) {
            const int c0 = nt * 8 + 2 * ql, c1 = c0 + 1;
#pragma unroll
            for (int e = 0; e < 4; ++e) sc[nt][e] *= 0.125f;
            if (t == qt) {
                if (c0 > r0l) sc[nt][0] = -1e9f;
                if (c1 > r0l) sc[nt][1] = -1e9f;
                if (c0 > r1l) sc[nt][2] = -1e9f;
                if (c1 > r1l) sc[nt][3] = -1e9f;
            }
            tm0 = fmaxf(tm0, fmaxf(sc[nt][0], sc[nt][1]));
            tm1 = fmaxf(tm1, fmaxf(sc[nt][2], sc[nt][3]));
        }
        tm0 = fmaxf(tm0, __shfl_xor_sync(0xffffffffu, tm0, 1));
        tm0 = fmaxf(tm0, __shfl_xor_sync(0xffffffffu, tm0, 2));
        tm1 = fmaxf(tm1, __shfl_xor_sync(0xffffffffu, tm1, 1));
        tm1 = fmaxf(tm1, __shfl_xor_sync(0xffffffffu, tm1, 2));

        const float nm0 = fmaxf(mrow0, tm0);
        const float nm1 = fmaxf(mrow1, tm1);
        const float al0 = __expf(mrow0 - nm0);
        const float al1 = __expf(mrow1 - nm1);
        float sum0 = 0.f, sum1 = 0.f;
#pragma unroll
        for (int nt = 0; nt < 8; ++nt) {
            sc[nt][0] = __expf(sc[nt][0] - nm0);
            sc[nt][1] = __expf(sc[nt][1] - nm0);
            sc[nt][2] = __expf(sc[nt][2] - nm1);
            sc[nt][3] = __expf(sc[nt][3] - nm1);
            sum0 += sc[nt][0] + sc[nt][1];
            sum1 += sc[nt][2] + sc[nt][3];
        }
        sum0 += __shfl_xor_sync(0xffffffffu, sum0, 1);
        sum0 += __shfl_xor_sync(0xffffffffu, sum0, 2);
        sum1 += __shfl_xor_sync(0xffffffffu, sum1, 1);
        sum1 += __shfl_xor_sync(0xffffffffu, sum1, 2);

        lrow0 = lrow0 * al0 + sum0;
        lrow1 = lrow1 * al1 + sum1;
        mrow0 = nm0; mrow1 = nm1;

#pragma unroll
        for (int nt = 0; nt < 8; ++nt) {
            o[nt][0] *= al0; o[nt][1] *= al0;
            o[nt][2] *= al1; o[nt][3] *= al1;
        }

        // ---- PV: P c-frag == fp16 a-frag after packing ----
#pragma unroll
        for (int ks = 0; ks < 4; ++ks) {
            uint32_t ap[4];
            ap[0] = packh2(sc[2 * ks    ][0], sc[2 * ks    ][1]);
            ap[1] = packh2(sc[2 * ks    ][2], sc[2 * ks    ][3]);
            ap[2] = packh2(sc[2 * ks + 1][0], sc[2 * ks + 1][1]);
            ap[3] = packh2(sc[2 * ks + 1][2], sc[2 * ks + 1][3]);
#pragma unroll
            for (int nt = 0; nt < 8; ++nt) {
                uint2 b = *(const uint2*)&sV[(nt * 4 + ks) * BF_SB + lane * 2];
                mma_f16(o[nt], ap, (const uint32_t*)&b);
            }
        }
    }

    // Epilogue -> fp16 [B,S,D]
    const float i0 = 1.f / lrow0, i1 = 1.f / lrow1;
    const int b = bh >> 4, h = bh & 15;
    const int s0 = qt * 64 + wm + qr, s1 = s0 + 8;
#pragma unroll
    for (int nt = 0; nt < 8; ++nt) {
        const int dk = nt * 8 + 2 * ql;
        __half* p0 = Out + ((size_t)(b * S_ + s0)) * D_ + h * DK_ + dk;
        *(uint32_t*)p0 = packh2(o[nt][0] * i0, o[nt][1] * i0);
        __half* p1 = Out + ((size_t)(b * S_ + s1)) * D_ + h * DK_ + dk;
        *(uint32_t*)p1 = packh2(o[nt][2] * i1, o[nt][3] * i1);
    }
}

// ============================================================================
// Launch
// ============================================================================
extern "C" void kernel_launch(void* const* d_in, const int* in_sizes, int n_in,
                              void* d_out, int out_size) {
    const float* q  = (const float*)d_in[0];
    const float* k  = (const float*)d_in[1];
    const float* v  = (const float*)d_in[2];
    // d_in[3] = mask (causal, known statically) — unused
    const float* Wq = (const float*)d_in[4];
    const float* Wk = (const float*)d_in[5];
    const float* Wv = (const float*)d_in[6];
    const float* Wo = (const float*)d_in[7];
    float* out = (float*)d_out;

    __half *qh, *kh, *vh, *wh, *Qh, *Kh, *Vh, *ah;
    cudaGetSymbolAddress((void**)&qh, g_qh);
    cudaGetSymbolAddress((void**)&kh, g_kh);
    cudaGetSymbolAddress((void**)&vh, g_vh);
    cudaGetSymbolAddress((void**)&wh, g_wh);
    cudaGetSymbolAddress((void**)&Qh, g_Qh);
    cudaGetSymbolAddress((void**)&Kh, g_Kh);
    cudaGetSymbolAddress((void**)&Vh, g_Vh);
    cudaGetSymbolAddress((void**)&ah, g_ah);

    cudaFuncSetAttribute(gemm_qkv, cudaFuncAttributeMaxDynamicSharedMemorySize, GEMM_SMEM);
    cudaFuncSetAttribute(gemm_out, cudaFuncAttributeMaxDynamicSharedMemorySize, GEMM_SMEM);

    // 1. fp32 -> fp16 converts
    cvt3<<<dim3((unsigned)(MD_ / 2048), 1, 3), 256>>>(q, k, v, qh, kh, vh);
    cvtw<<<dim3((unsigned)(DD_ / 2048), 1, 4), 256>>>(Wq, Wk, Wv, Wo, wh);

    // 2. Q/K/V projections (fp16 out, split heads)
    gemm_qkv<<<dim3(8, 64, 3), 256, GEMM_SMEM>>>(qh, kh, vh, wh, Qh, Kh, Vh);

    // 3. attention (fp16 in/out)
    attn_mma<<<dim3(S_ / 64, B_ * H_), 128>>>(Qh, Kh, Vh, ah);

    // 4. output projection (fp32 out)
    gemm_out<<<dim3(8, 64), 256, GEMM_SMEM>>>(ah, wh + 3 * DD_, out);
}